// round 11
// baseline (speedup 1.0000x reference)
#include <cuda_runtime.h>
#include <cuda_bf16.h>
#include <math.h>
#include <cstdint>

// Problem constants
#define BX   4
#define TT   1024
#define SS   1024
#define EE   1024
#define HH   16
#define DH   64

// Scratch (device globals; no allocation allowed)
__device__ float g_Q[BX * HH * TT * DH];   // [B,H,T,D]  tf32, pre-scaled by 1/8
__device__ float g_K[BX * HH * SS * DH];   // [B,H,S,D]  tf32
__device__ float g_Vt[BX * HH * DH * SS];  // [B,H,D,S]  tf32
__device__ float g_P[TT * BX * EE];        // [T,B,E]    tf32
__device__ float g_Wt[4 * EE * EE];        // W^T [N,K]  tf32
__device__ float g_Ar[BX * TT * EE];       // tgt tf32-rounded
__device__ float g_Br[BX * SS * EE];       // src tf32-rounded

// ---------------------------------------------------------------------------
// Helpers
// ---------------------------------------------------------------------------
__device__ __forceinline__ uint32_t smem_u32(const void* p) {
    uint32_t a;
    asm("{ .reg .u64 t; cvta.to.shared.u64 t, %1; cvt.u32.u64 %0, t; }" : "=r"(a) : "l"(p));
    return a;
}
__device__ __forceinline__ float tf32r(float x) {
    uint32_t u;
    asm("cvt.rna.tf32.f32 %0, %1;" : "=r"(u) : "f"(x));
    return __uint_as_float(u);
}
#define SWZ128(off) ((off) ^ (((off) >> 3) & 0x70))

__device__ __forceinline__ void cp16(uint32_t dst, const void* src) {
    asm volatile("cp.async.cg.shared.global [%0], [%1], 16;" :: "r"(dst), "l"(src));
}
#define CP_COMMIT() asm volatile("cp.async.commit_group;" ::: "memory")
#define CP_WAIT1()  asm volatile("cp.async.wait_group 1;" ::: "memory")
#define CP_WAIT0()  asm volatile("cp.async.wait_group 0;" ::: "memory")

__device__ __forceinline__ void ldsm4(uint32_t* r, uint32_t addr) {
    asm volatile("ldmatrix.sync.aligned.m8n8.x4.shared.b16 {%0,%1,%2,%3}, [%4];"
                 : "=r"(r[0]), "=r"(r[1]), "=r"(r[2]), "=r"(r[3]) : "r"(addr));
}
__device__ __forceinline__ void mma_tf32(float* d, const uint32_t* a, uint32_t b0, uint32_t b1) {
    asm volatile("mma.sync.aligned.m16n8k8.row.col.f32.tf32.tf32.f32 "
                 "{%0,%1,%2,%3}, {%4,%5,%6,%7}, {%8,%9}, {%0,%1,%2,%3};"
                 : "+f"(d[0]), "+f"(d[1]), "+f"(d[2]), "+f"(d[3])
                 : "r"(a[0]), "r"(a[1]), "r"(a[2]), "r"(a[3]), "r"(b0), "r"(b1));
}

// ---------------------------------------------------------------------------
// Elementwise tf32 rounding copies (z selects tensor)
// ---------------------------------------------------------------------------
__global__ __launch_bounds__(256)
void round_tf32_kernel(const float* __restrict__ a, const float* __restrict__ b,
                       float* __restrict__ oa, float* __restrict__ ob)
{
    const float* src = blockIdx.z ? b : a;
    float* dst = blockIdx.z ? ob : oa;
    const int n4 = (BX * TT * EE) / 4;
    for (int i = blockIdx.x * 256 + threadIdx.x; i < n4; i += gridDim.x * 256) {
        float4 v = ((const float4*)src)[i];
        v.x = tf32r(v.x); v.y = tf32r(v.y); v.z = tf32r(v.z); v.w = tf32r(v.w);
        ((float4*)dst)[i] = v;
    }
}

// ---------------------------------------------------------------------------
// Weight transpose + tf32 round, 4 weights in one launch (z selects)
// ---------------------------------------------------------------------------
__global__ __launch_bounds__(256)
void transpose_tf32_kernel(const float* __restrict__ W0, const float* __restrict__ W1,
                           const float* __restrict__ W2, const float* __restrict__ W3,
                           float* __restrict__ WtBase)
{
    __shared__ float tile[32][33];
    const int z = blockIdx.z;
    const float* W = (z == 0) ? W0 : (z == 1) ? W1 : (z == 2) ? W2 : W3;
    float* Wt = WtBase + (size_t)z * EE * EE;
    const int k0 = blockIdx.y * 32, n0 = blockIdx.x * 32;
    const int tx = threadIdx.x & 31, ty = threadIdx.x >> 5;
#pragma unroll
    for (int t = 0; t < 4; t++)
        tile[ty + 8 * t][tx] = W[(size_t)(k0 + ty + 8 * t) * EE + n0 + tx];
    __syncthreads();
#pragma unroll
    for (int t = 0; t < 4; t++)
        Wt[(size_t)(n0 + ty + 8 * t) * EE + k0 + tx] = tf32r(tile[tx][ty + 8 * t]);
}

// ---------------------------------------------------------------------------
// tf32 mma.sync GEMM body: 2 CTAs/SM, 3-stage cp.async, wait0 on last iter
// ---------------------------------------------------------------------------
#define GSMEM (3 * 32768 + 1024)

__device__ __forceinline__ void gemm_body(
    const float* __restrict__ A, const float* __restrict__ Bt,
    const float* __restrict__ bias, float* __restrict__ C,
    int mode, float scale, int L)
{
    extern __shared__ char dyn_sm[];
    char* sm = (char*)(((uintptr_t)dyn_sm + 1023) & ~(uintptr_t)1023);
    const uint32_t sb = smem_u32(sm);

    const int tid  = threadIdx.x;
    const int wid  = tid >> 5;
    const int lane = tid & 31;
    const int wm   = wid & 3;
    const int wn   = wid >> 2;
    const int m0 = blockIdx.y * 128;
    const int n0 = blockIdx.x * 128;

    const float* Ap = A  + (size_t)m0 * 1024;
    const float* Bp = Bt + (size_t)n0 * 1024;

    const int lrow  = ((lane >> 3) & 1) * 8 + (lane & 7);
    const int klane = lane >> 4;

    uint32_t aoff[2], asw[2], boff[4], bsw[4];
#pragma unroll
    for (int mt = 0; mt < 2; mt++) {
        int r = wm * 32 + mt * 16 + lrow;
        aoff[mt] = (uint32_t)r * 128;
        asw[mt]  = (uint32_t)(r & 7);
    }
#pragma unroll
    for (int nt = 0; nt < 4; nt++) {
        int r = wn * 64 + nt * 16 + lrow;
        boff[nt] = (uint32_t)r * 128;
        bsw[nt]  = (uint32_t)(r & 7);
    }

    float acc[2][8][4];
#pragma unroll
    for (int mt = 0; mt < 2; mt++)
#pragma unroll
        for (int nt = 0; nt < 8; nt++)
#pragma unroll
            for (int c = 0; c < 4; c++) acc[mt][nt][c] = 0.f;

    auto prefetch = [&](int st, int kt) {
        const int k0 = kt * 32;
        const uint32_t ao = sb + st * 32768;
        const uint32_t bo = ao + 16384;
#pragma unroll
        for (int t = 0; t < 4; t++) {
            int idx = tid + t * 256;
            int r = idx >> 3, c4 = idx & 7;
            uint32_t sw = SWZ128((uint32_t)(r * 128 + c4 * 16));
            cp16(ao + sw, Ap + (size_t)r * 1024 + k0 + c4 * 4);
            cp16(bo + sw, Bp + (size_t)r * 1024 + k0 + c4 * 4);
        }
    };

    prefetch(0, 0); CP_COMMIT();
    prefetch(1, 1); CP_COMMIT();

#pragma unroll 1
    for (int kt = 0; kt < 32; kt++) {
        if (kt == 31) { CP_WAIT0(); } else { CP_WAIT1(); }
        __syncthreads();
        if (kt + 2 < 32) prefetch((kt + 2) % 3, kt + 2);
        CP_COMMIT();

        const uint32_t ab = sb + (kt % 3) * 32768;
        const uint32_t bb = ab + 16384;
#pragma unroll
        for (int k8 = 0; k8 < 4; k8++) {
            const uint32_t kc = (uint32_t)(k8 * 2 + klane);
            uint32_t af[2][4], bf[4][4];
#pragma unroll
            for (int mt = 0; mt < 2; mt++)
                ldsm4(af[mt], ab + aoff[mt] + ((kc ^ asw[mt]) << 4));
#pragma unroll
            for (int nt = 0; nt < 4; nt++)
                ldsm4(bf[nt], bb + boff[nt] + ((kc ^ bsw[nt]) << 4));
#pragma unroll
            for (int mt = 0; mt < 2; mt++)
#pragma unroll
                for (int n8 = 0; n8 < 8; n8++) {
                    int bt = n8 >> 1, sub = n8 & 1;
                    mma_tf32(acc[mt][n8], af[mt], bf[bt][sub], bf[bt][sub + 2]);
                }
        }
    }

    const int rbase = lane >> 2;
    const int cbase = 2 * (lane & 3);
#pragma unroll
    for (int mt = 0; mt < 2; mt++) {
#pragma unroll
        for (int nt = 0; nt < 8; nt++) {
            int n = n0 + wn * 64 + nt * 8 + cbase;
#pragma unroll
            for (int half = 0; half < 2; half++) {
                int m = m0 + wm * 32 + mt * 16 + rbase + half * 8;
                float2 v;
                v.x = acc[mt][nt][half * 2 + 0];
                v.y = acc[mt][nt][half * 2 + 1];
                if (mode == 0) {
                    v.x += bias[n];
                    v.y += bias[n + 1];
                    *(float2*)&C[(size_t)m * 1024 + n] = v;
                } else if (mode == 1) {
                    int b = m / L, l = m % L;
                    size_t o = (((size_t)(b * HH + (n >> 6)) * L + l) * DH) + (n & 63);
                    v.x = tf32r(v.x * scale);
                    v.y = tf32r(v.y * scale);
                    *(float2*)&C[o] = v;
                } else {
                    int b = m / L, s = m % L;
                    size_t o = (((size_t)(b * HH + (n >> 6)) * DH) + (n & 63)) * (size_t)L + s;
                    C[o]     = tf32r(v.x);
                    C[o + L] = tf32r(v.y);
                }
            }
        }
    }
}

__global__ __launch_bounds__(256, 2)
void gemm_qkv_kernel(const float* __restrict__ Atgt, const float* __restrict__ Asrc,
                     const float* __restrict__ Wt,
                     float* __restrict__ Cq, float* __restrict__ Ck, float* __restrict__ Cvt)
{
    const int z = blockIdx.z;
    const float* A = (z == 0) ? Atgt : Asrc;
    const float* W = Wt + (size_t)z * EE * EE;
    float* C = (z == 0) ? Cq : (z == 1) ? Ck : Cvt;
    gemm_body(A, W, nullptr, C, (z == 2) ? 2 : 1, (z == 0) ? 0.125f : 1.0f, (z == 0) ? TT : SS);
}

__global__ __launch_bounds__(256, 2)
void gemm_out_kernel(const float* __restrict__ A, const float* __restrict__ Wt,
                     const float* __restrict__ bias, float* __restrict__ C)
{
    gemm_body(A, Wt, bias, C, 0, 1.0f, TT);
}

// ---------------------------------------------------------------------------
// Fused flash-style attention: 256 threads, 2 CTAs/SM, 64 t-rows/block,
// 16 iterations of 64-col tiles. K: 3 buffers; V: 3 buffers (buffer 2 reuses
// the dead Q staging region). Joint KV commit groups, ONE barrier per iter,
// prefetch issued right after the top sync. Last iter waits group 0.
// P never touches smem (shuffle permute); PV k-split 2, reduced at end.
// ---------------------------------------------------------------------------
#define AT2 64
// smem float offsets
#define F_Q    0                    // 64x64 Q staging; later V buffer 2   4096
#define F_K    4096                 // 3 x 64x64                         12288
#define F_V    16384                // 2 x 64x64 (V^T d x s)              8192
#define F_SP   24576                // spad row for b                     1024
#define F_PART 25600                // 2 x 64 partial row sums             128
#define F_SUM  25728                // 64 inv sums                          64
#define ATTN2_FLOATS 25792          // 103168 B
#define RED_PITCH 72                // k-split O reduce buffer (reuses F_K)

__global__ __launch_bounds__(256, 2)
void attn_kernel(const float* __restrict__ Q, const float* __restrict__ K,
                 const float* __restrict__ Vt,
                 const float* __restrict__ tpad, const float* __restrict__ spad,
                 const float* __restrict__ amask, const int* __restrict__ causal_p,
                 float* __restrict__ attn_out, float* __restrict__ P)
{
    extern __shared__ float smf[];
    const uint32_t q_b  = smem_u32(smf + F_Q);
    const uint32_t k_b  = smem_u32(smf + F_K);
    const uint32_t v_b  = smem_u32(smf + F_V);
    const uint32_t sp_b = smem_u32(smf + F_SP);
    float* s_sp   = smf + F_SP;
    float* s_part = smf + F_PART;
    float* s_sum  = smf + F_SUM;
    float* s_red  = smf + F_K;      // reused after main loop (barrier-guarded)

    const int tid = threadIdx.x;
    const int bh  = blockIdx.y;
    const int b   = bh >> 4;
    const int h   = bh & 15;
    const int t0  = blockIdx.x * AT2;
    const bool causal = (causal_p[0] != 0);

    const size_t qbase  = ((size_t)bh * TT + t0) * DH;
    const size_t kbase  = (size_t)bh * SS * DH;
    const size_t vtbase = (size_t)bh * DH * SS;

    const int lane  = tid & 31;
    const int wid   = tid >> 5;
    const int wm    = wid & 3;    // m16 group
    const int wn    = wid >> 2;   // n32 group (0/1); also PV k-split id
    const int lrow  = ((lane >> 3) & 1) * 8 + (lane & 7);
    const int klane = lane >> 4;
    const int rbase = lane >> 2;
    const int cbase = 2 * (lane & 3);

    const int r0 = wm * 16 + rbase;
    const int r1 = r0 + 8;
    const float tm0 = tpad[b * TT + t0 + r0];
    const float tm1 = tpad[b * TT + t0 + r1];

    // shuffle sources for C-layout -> A-fragment permute
    const int p_   = lane & 3;
    const int srcA = (lane & 28) | (p_ >> 1);
    const bool oddp = (p_ & 1);

    // buffer bases: V buffer 2 lives in the Q staging region
    auto kbuf = [&](int it) -> uint32_t { return k_b + (uint32_t)(it % 3) * 16384; };
    auto vbuf = [&](int it) -> uint32_t {
        int s = it % 3;
        return (s == 2) ? q_b : (v_b + (uint32_t)s * 16384);
    };

    auto prefetch_kv = [&](int it) {
        const uint32_t kb = kbuf(it);
        const uint32_t vb = vbuf(it);
        const int c0 = it * 64;
#pragma unroll
        for (int t = 0; t < 4; t++) {
            int idx = tid + t * 256;
            int r = idx >> 4, c = idx & 15;
            cp16(kb + r * 256 + ((c ^ (r & 7)) << 4),
                 K + kbase + (size_t)(c0 + r) * DH + c * 4);
            cp16(vb + r * 256 + ((c ^ (r & 7)) << 4),
                 Vt + vtbase + (size_t)r * SS + c0 + c * 4);
        }
    };

    // prologue: [Q + spad + KV0] , [KV1]
    {
#pragma unroll
        for (int t = 0; t < 4; t++) {
            int idx = tid + t * 256;
            int r = idx >> 4, c = idx & 15;
            cp16(q_b + r * 256 + ((c ^ (r & 7)) << 4), Q + qbase + (size_t)r * DH + c * 4);
        }
        cp16(sp_b + tid * 16, spad + b * SS + tid * 4);
    }
    prefetch_kv(0);
    CP_COMMIT();
    prefetch_kv(1);
    CP_COMMIT();

    CP_WAIT1();            // group0 (Q, spad, KV0) complete
    __syncthreads();

    // preload Q fragments (m16 rows wm*16.., k=64), then release Q region
    const int arow = wm * 16 + lrow;
    uint32_t qf[8][4];
#pragma unroll
    for (int k8 = 0; k8 < 8; k8++) {
        uint32_t kc = (uint32_t)(k8 * 2 + klane);
        ldsm4(qf[k8], q_b + arow * 256 + ((kc ^ (uint32_t)(arow & 7)) << 4));
    }
    __syncthreads();       // Q frags in regs everywhere before V2 overwrites Q region

    const int brow0 = wn * 32 + lrow;        // K rows (first n16 of this n32)
    const int brow1 = brow0 + 16;            // second n16

    float rs0 = 0.f, rs1 = 0.f;
    float oacc[8][4];                        // m16 x n64 partial (own k slice)
#pragma unroll
    for (int n8 = 0; n8 < 8; n8++)
#pragma unroll
        for (int c = 0; c < 4; c++) oacc[n8][c] = 0.f;

#pragma unroll 1
    for (int it = 0; it < 16; it++) {
        if (it > 0) {
            if (it == 15) { CP_WAIT0(); } else { CP_WAIT1(); }
            __syncthreads();
        }
        // prefetch (it+2): safe — that buffer was last read in it-1 (sync'd)
        if (it + 2 < 16) prefetch_kv(it + 2);
        CP_COMMIT();

        const int c0 = it * 64;
        const uint32_t kb = kbuf(it);
        const uint32_t vb = vbuf(it);

        // mask loads early
        float2 am[4][2];
#pragma unroll
        for (int n8 = 0; n8 < 4; n8++) {
            int sc = c0 + wn * 32 + n8 * 8 + cbase;
            am[n8][0] = *(const float2*)&amask[((size_t)b * TT + t0 + r0) * SS + sc];
            am[n8][1] = *(const float2*)&amask[((size_t)b * TT + t0 + r1) * SS + sc];
        }

        // S = Q @ K^T  (warp m16 x n32)
        float acc[4][4];
#pragma unroll
        for (int n8 = 0; n8 < 4; n8++)
#pragma unroll
            for (int c = 0; c < 4; c++) acc[n8][c] = 0.f;

#pragma unroll
        for (int k8 = 0; k8 < 8; k8++) {
            uint32_t kc = (uint32_t)(k8 * 2 + klane);
            uint32_t bf0[4], bf1[4];
            ldsm4(bf0, kb + brow0 * 256 + ((kc ^ (uint32_t)(brow0 & 7)) << 4));
            ldsm4(bf1, kb + brow1 * 256 + ((kc ^ (uint32_t)(brow1 & 7)) << 4));
            mma_tf32(acc[0], qf[k8], bf0[0], bf0[2]);
            mma_tf32(acc[1], qf[k8], bf0[1], bf0[3]);
            mma_tf32(acc[2], qf[k8], bf1[0], bf1[2]);
            mma_tf32(acc[3], qf[k8], bf1[1], bf1[3]);
        }

        // exp (no max shift), attn write (unnormalized), row sums, tf32 round
        const int tg0 = t0 + r0, tg1 = t0 + r1;
#pragma unroll
        for (int n8 = 0; n8 < 4; n8++) {
            int scl = wn * 32 + n8 * 8 + cbase;
            int sc  = c0 + scl;
            float2 sp = *(const float2*)&s_sp[sc];

            float m00 = tm0 * sp.x * am[n8][0].x;
            float m01 = tm0 * sp.y * am[n8][0].y;
            float m10 = tm1 * sp.x * am[n8][1].x;
            float m11 = tm1 * sp.y * am[n8][1].y;
            if (causal) {
                if (sc > tg0)     m00 = 0.f;
                if (sc + 1 > tg0) m01 = 0.f;
                if (sc > tg1)     m10 = 0.f;
                if (sc + 1 > tg1) m11 = 0.f;
            }
            float e00 = __expf(acc[n8][0] + m00);
            float e01 = __expf(acc[n8][1] + m01);
            float e10 = __expf(acc[n8][2] + m10);
            float e11 = __expf(acc[n8][3] + m11);
            rs0 += e00 + e01;
            rs1 += e10 + e11;

            if (attn_out) {
                float2 w0 = {e00, e01}, w1 = {e10, e11};
                *(float2*)&attn_out[((size_t)bh * TT + tg0) * SS + sc] = w0;
                *(float2*)&attn_out[((size_t)bh * TT + tg1) * SS + sc] = w1;
            }
            // keep tf32-rounded P in registers (C layout)
            acc[n8][0] = tf32r(e00);
            acc[n8][1] = tf32r(e01);
            acc[n8][2] = tf32r(e10);
            acc[n8][3] = tf32r(e11);
        }

        // O += P @ V over this warp's own 32 k-columns (A-frags via shuffles)
#pragma unroll
        for (int j = 0; j < 4; j++) {
            float u0 = __shfl_sync(0xffffffffu, acc[j][0], srcA);
            float u1 = __shfl_sync(0xffffffffu, acc[j][1], srcA);
            float v0 = __shfl_sync(0xffffffffu, acc[j][2], srcA);
            float v1 = __shfl_sync(0xffffffffu, acc[j][3], srcA);
            float w0 = __shfl_sync(0xffffffffu, acc[j][0], srcA + 2);
            float w1 = __shfl_sync(0xffffffffu, acc[j][1], srcA + 2);
            float x0 = __shfl_sync(0xffffffffu, acc[j][2], srcA + 2);
            float x1 = __shfl_sync(0xffffffffu, acc[j][3], srcA + 2);
            uint32_t af[4];
            af[0] = __float_as_uint(oddp ? u1 : u0);
            af[1] = __float_as_uint(oddp ? v1 : v0);
            af[2] = __float_as_uint(oddp ? w1 : w0);
            af[3] = __float_as_uint(oddp ? x1 : x0);

            uint32_t kc = (uint32_t)((wn * 4 + j) * 2 + klane);
#pragma unroll
            for (int nt = 0; nt < 4; nt++) {
                int br = nt * 16 + lrow;
                uint32_t bf[4];
                ldsm4(bf, vb + br * 256 + ((kc ^ (uint32_t)(br & 7)) << 4));
                mma_tf32(oacc[2 * nt],     af, bf[0], bf[2]);
                mma_tf32(oacc[2 * nt + 1], af, bf[1], bf[3]);
            }
        }
        // no bottom barrier: 3-deep buffers make next iter's prefetch safe
    }

    // row-sum reduction: quad shuffle, then 2-way cross-warp via smem
    rs0 += __shfl_xor_sync(0xffffffffu, rs0, 1);
    rs0 += __shfl_xor_sync(0xffffffffu, rs0, 2);
    rs1 += __shfl_xor_sync(0xffffffffu, rs1, 1);
    rs1 += __shfl_xor_sync(0xffffffffu, rs1, 2);

    __syncthreads();   // all warps out of main loop before s_red reuses K buffers

    if ((lane & 3) == 0) {
        s_part[wn * 64 + r0] = rs0;
        s_part[wn * 64 + r1] = rs1;
    }
    // k-split partials: wn==1 stores O partial to s_red (reuses K buffer)
    if (wn == 1) {
#pragma unroll
        for (int n8 = 0; n8 < 8; n8++) {
            int cc = n8 * 8 + cbase;
            *(float2*)&s_red[r0 * RED_PITCH + cc] = *(float2*)&oacc[n8][0];
            *(float2*)&s_red[r1 * RED_PITCH + cc] = *(float2*)&oacc[n8][2];
        }
    }
    if (attn_out) asm volatile("membar.cta;" ::: "memory");
    __syncthreads();
    if (tid < 64) {
        s_sum[tid] = 1.f / (s_part[tid] + s_part[64 + tid]);
    }
    __syncthreads();

    // wn==0 warps: combine k-split partials, scale, write P gmem (tf32)
    if (wn == 0) {
        float inv0 = s_sum[r0], inv1 = s_sum[r1];
#pragma unroll
        for (int n8 = 0; n8 < 8; n8++) {
            int cc = n8 * 8 + cbase;
            float2 q0 = *(float2*)&s_red[r0 * RED_PITCH + cc];
            float2 q1 = *(float2*)&s_red[r1 * RED_PITCH + cc];
            float2 v0 = {tf32r((oacc[n8][0] + q0.x) * inv0), tf32r((oacc[n8][1] + q0.y) * inv0)};
            float2 v1 = {tf32r((oacc[n8][2] + q1.x) * inv1), tf32r((oacc[n8][3] + q1.y) * inv1)};
            *(float2*)&P[((size_t)(t0 + r0) * BX + b) * EE + h * DH + cc] = v0;
            *(float2*)&P[((size_t)(t0 + r1) * BX + b) * EE + h * DH + cc] = v1;
        }
    }

    // rescale this block's attn rows (unnormalized -> probabilities)
    if (attn_out) {
        const int r = tid >> 2;
        const int l4 = tid & 3;
        const float inv = s_sum[r];
        float* row = attn_out + ((size_t)bh * TT + t0 + r) * SS;
#pragma unroll 8
        for (int i = 0; i < 64; i++) {
            float4 v = *(float4*)&row[l4 * 4 + i * 16];
            v.x *= inv; v.y *= inv; v.z *= inv; v.w *= inv;
            *(float4*)&row[l4 * 4 + i * 16] = v;
        }
    }
}

// ---------------------------------------------------------------------------
// Launch
// ---------------------------------------------------------------------------
extern "C" void kernel_launch(void* const* d_in, const int* in_sizes, int n_in,
                              void* d_out, int out_size)
{
    const float* src   = (const float*)d_in[0];
    const float* tgt   = (const float*)d_in[1];
    const float* spad  = (const float*)d_in[2];
    const float* tpad  = (const float*)d_in[3];
    const float* amask = (const float*)d_in[4];
    const int*   caus  = (const int*)  d_in[5];
    const float* Wq    = (const float*)d_in[6];
    const float* Wk    = (const float*)d_in[7];
    const float* Wv    = (const float*)d_in[8];
    const float* Wo    = (const float*)d_in[9];
    const float* bo    = (const float*)d_in[10];

    const size_t OUT_N  = (size_t)TT * BX * EE;
    const size_t ATTN_N = (size_t)BX * HH * TT * SS;

    float* out_p  = nullptr;
    float* attn_p = nullptr;
    if ((size_t)out_size == OUT_N + ATTN_N) {
        out_p  = (float*)d_out;
        attn_p = (float*)d_out + OUT_N;
    } else if ((size_t)out_size == ATTN_N) {
        attn_p = (float*)d_out;
    } else {
        out_p  = (float*)d_out;
    }

    float *Qp, *Kp, *Vtp, *Pp, *Wtp, *Arp, *Brp;
    cudaGetSymbolAddress((void**)&Qp, g_Q);
    cudaGetSymbolAddress((void**)&Kp, g_K);
    cudaGetSymbolAddress((void**)&Vtp, g_Vt);
    cudaGetSymbolAddress((void**)&Pp, g_P);
    cudaGetSymbolAddress((void**)&Wtp, g_Wt);
    cudaGetSymbolAddress((void**)&Arp, g_Ar);
    cudaGetSymbolAddress((void**)&Brp, g_Br);

    const int ATTN_SMEM = ATTN2_FLOATS * (int)sizeof(float);
    cudaFuncSetAttribute(attn_kernel, cudaFuncAttributeMaxDynamicSharedMemorySize, ATTN_SMEM);
    cudaFuncSetAttribute(gemm_qkv_kernel, cudaFuncAttributeMaxDynamicSharedMemorySize, GSMEM);
    cudaFuncSetAttribute(gemm_out_kernel, cudaFuncAttributeMaxDynamicSharedMemorySize, GSMEM);

    // pre-round inputs + transpose weights
    round_tf32_kernel<<<dim3(512, 1, 2), 256>>>(tgt, src, Arp, Brp);
    transpose_tf32_kernel<<<dim3(32, 32, 4), 256>>>(Wq, Wk, Wv, Wo, Wtp);

    // merged QKV projections (2 CTAs/SM)
    gemm_qkv_kernel<<<dim3(8, 32, 3), 256, GSMEM>>>(Arp, Brp, Wtp, Qp, Kp, Vtp);

    // fused attention (2 CTAs/SM)
    dim3 agrid(TT / AT2, BX * HH);   // (16, 64)
    attn_kernel<<<agrid, dim3(256), ATTN_SMEM>>>(Qp, Kp, Vtp, tpad, spad, amask,
                                                 caus, attn_p, Pp);

    // output projection (2 CTAs/SM)
    if (out_p) {
        gemm_out_kernel<<<dim3(8, 32), 256, GSMEM>>>(Pp, Wtp + 3 * (size_t)EE * EE, bo, out_p);
    }
}

// round 12
// speedup vs baseline: 1.0103x; 1.0103x over previous
#include <cuda_runtime.h>
#include <cuda_bf16.h>
#include <math.h>
#include <cstdint>

// Problem constants
#define BX   4
#define TT   1024
#define SS   1024
#define EE   1024
#define HH   16
#define DH   64

// Scratch (device globals; no allocation allowed)
__device__ float g_Q[BX * HH * TT * DH];   // [B,H,T,D]  tf32, pre-scaled by 1/8
__device__ float g_K[BX * HH * SS * DH];   // [B,H,S,D]  tf32
__device__ float g_Vt[BX * HH * DH * SS];  // [B,H,D,S]  tf32
__device__ float g_P[TT * BX * EE];        // [T,B,E]    tf32
__device__ float g_Wt[4 * EE * EE];        // W^T [N,K]  tf32
__device__ float g_Ar[BX * TT * EE];       // tgt tf32-rounded
__device__ float g_Br[BX * SS * EE];       // src tf32-rounded

// ---------------------------------------------------------------------------
// Helpers
// ---------------------------------------------------------------------------
__device__ __forceinline__ uint32_t smem_u32(const void* p) {
    uint32_t a;
    asm("{ .reg .u64 t; cvta.to.shared.u64 t, %1; cvt.u32.u64 %0, t; }" : "=r"(a) : "l"(p));
    return a;
}
__device__ __forceinline__ float tf32r(float x) {
    uint32_t u;
    asm("cvt.rna.tf32.f32 %0, %1;" : "=r"(u) : "f"(x));
    return __uint_as_float(u);
}
#define SWZ128(off) ((off) ^ (((off) >> 3) & 0x70))

__device__ __forceinline__ void cp16(uint32_t dst, const void* src) {
    asm volatile("cp.async.cg.shared.global [%0], [%1], 16;" :: "r"(dst), "l"(src));
}
#define CP_COMMIT() asm volatile("cp.async.commit_group;" ::: "memory")
#define CP_WAIT1()  asm volatile("cp.async.wait_group 1;" ::: "memory")

__device__ __forceinline__ void ldsm4(uint32_t* r, uint32_t addr) {
    asm volatile("ldmatrix.sync.aligned.m8n8.x4.shared.b16 {%0,%1,%2,%3}, [%4];"
                 : "=r"(r[0]), "=r"(r[1]), "=r"(r[2]), "=r"(r[3]) : "r"(addr));
}
__device__ __forceinline__ void mma_tf32(float* d, const uint32_t* a, uint32_t b0, uint32_t b1) {
    asm volatile("mma.sync.aligned.m16n8k8.row.col.f32.tf32.tf32.f32 "
                 "{%0,%1,%2,%3}, {%4,%5,%6,%7}, {%8,%9}, {%0,%1,%2,%3};"
                 : "+f"(d[0]), "+f"(d[1]), "+f"(d[2]), "+f"(d[3])
                 : "r"(a[0]), "r"(a[1]), "r"(a[2]), "r"(a[3]), "r"(b0), "r"(b1));
}

// ---------------------------------------------------------------------------
// Elementwise tf32 rounding copies (z selects tensor)
// ---------------------------------------------------------------------------
__global__ __launch_bounds__(256)
void round_tf32_kernel(const float* __restrict__ a, const float* __restrict__ b,
                       float* __restrict__ oa, float* __restrict__ ob)
{
    const float* src = blockIdx.z ? b : a;
    float* dst = blockIdx.z ? ob : oa;
    const int n4 = (BX * TT * EE) / 4;
    for (int i = blockIdx.x * 256 + threadIdx.x; i < n4; i += gridDim.x * 256) {
        float4 v = ((const float4*)src)[i];
        v.x = tf32r(v.x); v.y = tf32r(v.y); v.z = tf32r(v.z); v.w = tf32r(v.w);
        ((float4*)dst)[i] = v;
    }
}

// ---------------------------------------------------------------------------
// Weight transpose + tf32 round, 4 weights in one launch (z selects)
// ---------------------------------------------------------------------------
__global__ __launch_bounds__(256)
void transpose_tf32_kernel(const float* __restrict__ W0, const float* __restrict__ W1,
                           const float* __restrict__ W2, const float* __restrict__ W3,
                           float* __restrict__ WtBase)
{
    __shared__ float tile[32][33];
    const int z = blockIdx.z;
    const float* W = (z == 0) ? W0 : (z == 1) ? W1 : (z == 2) ? W2 : W3;
    float* Wt = WtBase + (size_t)z * EE * EE;
    const int k0 = blockIdx.y * 32, n0 = blockIdx.x * 32;
    const int tx = threadIdx.x & 31, ty = threadIdx.x >> 5;
#pragma unroll
    for (int t = 0; t < 4; t++)
        tile[ty + 8 * t][tx] = W[(size_t)(k0 + ty + 8 * t) * EE + n0 + tx];
    __syncthreads();
#pragma unroll
    for (int t = 0; t < 4; t++)
        Wt[(size_t)(n0 + ty + 8 * t) * EE + k0 + tx] = tf32r(tile[tx][ty + 8 * t]);
}

// ---------------------------------------------------------------------------
// tf32 mma.sync GEMM body (R10 verbatim): 2 CTAs/SM, 3-stage cp.async
// ---------------------------------------------------------------------------
#define GSMEM (3 * 32768 + 1024)

__device__ __forceinline__ void gemm_body(
    const float* __restrict__ A, const float* __restrict__ Bt,
    const float* __restrict__ bias, float* __restrict__ C,
    int mode, float scale, int L)
{
    extern __shared__ char dyn_sm[];
    char* sm = (char*)(((uintptr_t)dyn_sm + 1023) & ~(uintptr_t)1023);
    const uint32_t sb = smem_u32(sm);

    const int tid  = threadIdx.x;
    const int wid  = tid >> 5;
    const int lane = tid & 31;
    const int wm   = wid & 3;
    const int wn   = wid >> 2;
    const int m0 = blockIdx.y * 128;
    const int n0 = blockIdx.x * 128;

    const float* Ap = A  + (size_t)m0 * 1024;
    const float* Bp = Bt + (size_t)n0 * 1024;

    const int lrow  = ((lane >> 3) & 1) * 8 + (lane & 7);
    const int klane = lane >> 4;

    uint32_t aoff[2], asw[2], boff[4], bsw[4];
#pragma unroll
    for (int mt = 0; mt < 2; mt++) {
        int r = wm * 32 + mt * 16 + lrow;
        aoff[mt] = (uint32_t)r * 128;
        asw[mt]  = (uint32_t)(r & 7);
    }
#pragma unroll
    for (int nt = 0; nt < 4; nt++) {
        int r = wn * 64 + nt * 16 + lrow;
        boff[nt] = (uint32_t)r * 128;
        bsw[nt]  = (uint32_t)(r & 7);
    }

    float acc[2][8][4];
#pragma unroll
    for (int mt = 0; mt < 2; mt++)
#pragma unroll
        for (int nt = 0; nt < 8; nt++)
#pragma unroll
            for (int c = 0; c < 4; c++) acc[mt][nt][c] = 0.f;

    auto prefetch = [&](int st, int kt) {
        const int k0 = kt * 32;
        const uint32_t ao = sb + st * 32768;
        const uint32_t bo = ao + 16384;
#pragma unroll
        for (int t = 0; t < 4; t++) {
            int idx = tid + t * 256;
            int r = idx >> 3, c4 = idx & 7;
            uint32_t sw = SWZ128((uint32_t)(r * 128 + c4 * 16));
            cp16(ao + sw, Ap + (size_t)r * 1024 + k0 + c4 * 4);
            cp16(bo + sw, Bp + (size_t)r * 1024 + k0 + c4 * 4);
        }
    };

    prefetch(0, 0); CP_COMMIT();
    prefetch(1, 1); CP_COMMIT();

#pragma unroll 1
    for (int kt = 0; kt < 32; kt++) {
        CP_WAIT1();
        __syncthreads();
        if (kt + 2 < 32) prefetch((kt + 2) % 3, kt + 2);
        CP_COMMIT();

        const uint32_t ab = sb + (kt % 3) * 32768;
        const uint32_t bb = ab + 16384;
#pragma unroll
        for (int k8 = 0; k8 < 4; k8++) {
            const uint32_t kc = (uint32_t)(k8 * 2 + klane);
            uint32_t af[2][4], bf[4][4];
#pragma unroll
            for (int mt = 0; mt < 2; mt++)
                ldsm4(af[mt], ab + aoff[mt] + ((kc ^ asw[mt]) << 4));
#pragma unroll
            for (int nt = 0; nt < 4; nt++)
                ldsm4(bf[nt], bb + boff[nt] + ((kc ^ bsw[nt]) << 4));
#pragma unroll
            for (int mt = 0; mt < 2; mt++)
#pragma unroll
                for (int n8 = 0; n8 < 8; n8++) {
                    int bt = n8 >> 1, sub = n8 & 1;
                    mma_tf32(acc[mt][n8], af[mt], bf[bt][sub], bf[bt][sub + 2]);
                }
        }
    }

    const int rbase = lane >> 2;
    const int cbase = 2 * (lane & 3);
#pragma unroll
    for (int mt = 0; mt < 2; mt++) {
#pragma unroll
        for (int nt = 0; nt < 8; nt++) {
            int n = n0 + wn * 64 + nt * 8 + cbase;
#pragma unroll
            for (int half = 0; half < 2; half++) {
                int m = m0 + wm * 32 + mt * 16 + rbase + half * 8;
                float2 v;
                v.x = acc[mt][nt][half * 2 + 0];
                v.y = acc[mt][nt][half * 2 + 1];
                if (mode == 0) {
                    v.x += bias[n];
                    v.y += bias[n + 1];
                    *(float2*)&C[(size_t)m * 1024 + n] = v;
                } else if (mode == 1) {
                    int b = m / L, l = m % L;
                    size_t o = (((size_t)(b * HH + (n >> 6)) * L + l) * DH) + (n & 63);
                    v.x = tf32r(v.x * scale);
                    v.y = tf32r(v.y * scale);
                    *(float2*)&C[o] = v;
                } else {
                    int b = m / L, s = m % L;
                    size_t o = (((size_t)(b * HH + (n >> 6)) * DH) + (n & 63)) * (size_t)L + s;
                    C[o]     = tf32r(v.x);
                    C[o + L] = tf32r(v.y);
                }
            }
        }
    }
}

__global__ __launch_bounds__(256, 2)
void gemm_qkv_kernel(const float* __restrict__ Atgt, const float* __restrict__ Asrc,
                     const float* __restrict__ Wt,
                     float* __restrict__ Cq, float* __restrict__ Ck, float* __restrict__ Cvt)
{
    const int z = blockIdx.z;
    const float* A = (z == 0) ? Atgt : Asrc;
    const float* W = Wt + (size_t)z * EE * EE;
    float* C = (z == 0) ? Cq : (z == 1) ? Ck : Cvt;
    gemm_body(A, W, nullptr, C, (z == 2) ? 2 : 1, (z == 0) ? 0.125f : 1.0f, (z == 0) ? TT : SS);
}

__global__ __launch_bounds__(256, 2)
void gemm_out_kernel(const float* __restrict__ A, const float* __restrict__ Wt,
                     const float* __restrict__ bias, float* __restrict__ C)
{
    gemm_body(A, Wt, bias, C, 0, 1.0f, TT);
}

// ---------------------------------------------------------------------------
// Fused flash-style attention (R10 structure): 256 threads, 2 CTAs/SM.
// NEW: attn_out writes go through a per-warp smem staging tile so the gmem
// stores are fully coalesced STG.128 (was 8-row-scattered STG.64). No block
// barriers added (warp-private staging + __syncwarp).
// ---------------------------------------------------------------------------
#define AT2 64
// smem float offsets
#define F_Q     0                   // 64x64, rows 256B swizzled      4096
#define F_K     4096                // 2 x 64x64                      8192
#define F_V     12288               // 2 x 64x64 (V^T d x s)          8192
#define F_SP    20480               // spad row for b                 1024
#define F_PART  21504               // 2 x 64 partial row sums         128
#define F_SUM   21632               // 64 inv sums                      64
#define F_STAGE 21696               // 8 warps x 16x36 stage          4608
#define ATTN2_FLOATS 26304          // 105216 B
#define RED_PITCH 72                // k-split O reduce buffer (reuses F_K)
#define STG_PITCH 36

__global__ __launch_bounds__(256, 2)
void attn_kernel(const float* __restrict__ Q, const float* __restrict__ K,
                 const float* __restrict__ Vt,
                 const float* __restrict__ tpad, const float* __restrict__ spad,
                 const float* __restrict__ amask, const int* __restrict__ causal_p,
                 float* __restrict__ attn_out, float* __restrict__ P)
{
    extern __shared__ float smf[];
    const uint32_t q_b  = smem_u32(smf + F_Q);
    const uint32_t k_b  = smem_u32(smf + F_K);
    const uint32_t v_b  = smem_u32(smf + F_V);
    const uint32_t sp_b = smem_u32(smf + F_SP);
    float* s_sp   = smf + F_SP;
    float* s_part = smf + F_PART;
    float* s_sum  = smf + F_SUM;
    float* s_red  = smf + F_K;      // reused after main loop

    const int tid = threadIdx.x;
    const int bh  = blockIdx.y;
    const int b   = bh >> 4;
    const int h   = bh & 15;
    const int t0  = blockIdx.x * AT2;
    const bool causal = (causal_p[0] != 0);

    const size_t qbase  = ((size_t)bh * TT + t0) * DH;
    const size_t kbase  = (size_t)bh * SS * DH;
    const size_t vtbase = (size_t)bh * DH * SS;

    const int lane  = tid & 31;
    const int wid   = tid >> 5;
    const int wm    = wid & 3;    // m16 group
    const int wn    = wid >> 2;   // n32 group (0/1); also PV k-split id
    const int lrow  = ((lane >> 3) & 1) * 8 + (lane & 7);
    const int klane = lane >> 4;
    const int rbase = lane >> 2;
    const int cbase = 2 * (lane & 3);

    float* s_stage = smf + F_STAGE + wid * (16 * STG_PITCH);

    const int r0 = wm * 16 + rbase;
    const int r1 = r0 + 8;
    const float tm0 = tpad[b * TT + t0 + r0];
    const float tm1 = tpad[b * TT + t0 + r1];

    // shuffle sources for C-layout -> A-fragment permute
    const int p_   = lane & 3;
    const int srcA = (lane & 28) | (p_ >> 1);
    const bool oddp = (p_ & 1);

    auto prefetch_kv = [&](int it) {
        const uint32_t kb = k_b + (uint32_t)(it & 1) * 16384;
        const uint32_t vb = v_b + (uint32_t)(it & 1) * 16384;
        const int c0 = it * 64;
#pragma unroll
        for (int t = 0; t < 4; t++) {
            int idx = tid + t * 256;
            int r = idx >> 4, c = idx & 15;
            cp16(kb + r * 256 + ((c ^ (r & 7)) << 4),
                 K + kbase + (size_t)(c0 + r) * DH + c * 4);
            cp16(vb + r * 256 + ((c ^ (r & 7)) << 4),
                 Vt + vtbase + (size_t)r * SS + c0 + c * 4);
        }
    };

    // prologue: Q + spad + KV0 | KV1
    {
#pragma unroll
        for (int t = 0; t < 4; t++) {
            int idx = tid + t * 256;
            int r = idx >> 4, c = idx & 15;
            cp16(q_b + r * 256 + ((c ^ (r & 7)) << 4), Q + qbase + (size_t)r * DH + c * 4);
        }
        cp16(sp_b + tid * 16, spad + b * SS + tid * 4);
    }
    prefetch_kv(0);
    CP_COMMIT();
    prefetch_kv(1);
    CP_COMMIT();

    CP_WAIT1();
    __syncthreads();

    // preload Q fragments (m16 rows wm*16.., k=64)
    const int arow = wm * 16 + lrow;
    uint32_t qf[8][4];
#pragma unroll
    for (int k8 = 0; k8 < 8; k8++) {
        uint32_t kc = (uint32_t)(k8 * 2 + klane);
        ldsm4(qf[k8], q_b + arow * 256 + ((kc ^ (uint32_t)(arow & 7)) << 4));
    }
    const int brow0 = wn * 32 + lrow;        // K rows (first n16 of this n32)
    const int brow1 = brow0 + 16;            // second n16

    float rs0 = 0.f, rs1 = 0.f;
    float oacc[8][4];                        // m16 x n64 partial (own k slice)
#pragma unroll
    for (int n8 = 0; n8 < 8; n8++)
#pragma unroll
        for (int c = 0; c < 4; c++) oacc[n8][c] = 0.f;

#pragma unroll 1
    for (int it = 0; it < 16; it++) {
        if (it > 0) {
            CP_WAIT1();
            __syncthreads();
        }
        const int c0 = it * 64;
        const uint32_t kb = k_b + (uint32_t)(it & 1) * 16384;
        const uint32_t vb = v_b + (uint32_t)(it & 1) * 16384;

        // mask loads early
        float2 am[4][2];
#pragma unroll
        for (int n8 = 0; n8 < 4; n8++) {
            int sc = c0 + wn * 32 + n8 * 8 + cbase;
            am[n8][0] = *(const float2*)&amask[((size_t)b * TT + t0 + r0) * SS + sc];
            am[n8][1] = *(const float2*)&amask[((size_t)b * TT + t0 + r1) * SS + sc];
        }

        // S = Q @ K^T  (warp m16 x n32)
        float acc[4][4];
#pragma unroll
        for (int n8 = 0; n8 < 4; n8++)
#pragma unroll
            for (int c = 0; c < 4; c++) acc[n8][c] = 0.f;

#pragma unroll
        for (int k8 = 0; k8 < 8; k8++) {
            uint32_t kc = (uint32_t)(k8 * 2 + klane);
            uint32_t bf0[4], bf1[4];
            ldsm4(bf0, kb + brow0 * 256 + ((kc ^ (uint32_t)(brow0 & 7)) << 4));
            ldsm4(bf1, kb + brow1 * 256 + ((kc ^ (uint32_t)(brow1 & 7)) << 4));
            mma_tf32(acc[0], qf[k8], bf0[0], bf0[2]);
            mma_tf32(acc[1], qf[k8], bf0[1], bf0[3]);
            mma_tf32(acc[2], qf[k8], bf1[0], bf1[2]);
            mma_tf32(acc[3], qf[k8], bf1[1], bf1[3]);
        }

        // exp (no max shift), stage unnormalized attn in warp-private smem,
        // row sums, tf32 round regs for PV
        const int tg0 = t0 + r0, tg1 = t0 + r1;
#pragma unroll
        for (int n8 = 0; n8 < 4; n8++) {
            int scl = wn * 32 + n8 * 8 + cbase;
            int sc  = c0 + scl;
            float2 sp = *(const float2*)&s_sp[sc];

            float m00 = tm0 * sp.x * am[n8][0].x;
            float m01 = tm0 * sp.y * am[n8][0].y;
            float m10 = tm1 * sp.x * am[n8][1].x;
            float m11 = tm1 * sp.y * am[n8][1].y;
            if (causal) {
                if (sc > tg0)     m00 = 0.f;
                if (sc + 1 > tg0) m01 = 0.f;
                if (sc > tg1)     m10 = 0.f;
                if (sc + 1 > tg1) m11 = 0.f;
            }
            float e00 = __expf(acc[n8][0] + m00);
            float e01 = __expf(acc[n8][1] + m01);
            float e10 = __expf(acc[n8][2] + m10);
            float e11 = __expf(acc[n8][3] + m11);
            rs0 += e00 + e01;
            rs1 += e10 + e11;

            if (attn_out) {
                int cl = n8 * 8 + cbase;   // local col within warp tile 0..31
                float2 w0 = {e00, e01}, w1 = {e10, e11};
                *(float2*)&s_stage[rbase * STG_PITCH + cl]       = w0;
                *(float2*)&s_stage[(rbase + 8) * STG_PITCH + cl] = w1;
            }
            // keep tf32-rounded P in registers (C layout)
            acc[n8][0] = tf32r(e00);
            acc[n8][1] = tf32r(e01);
            acc[n8][2] = tf32r(e10);
            acc[n8][3] = tf32r(e11);
        }

        // coalesced attn_out store from warp-private stage (STG.128)
        if (attn_out) {
            __syncwarp();
            const int rl = lane >> 3;            // 0..3
            const int cl = (lane & 7) * 4;       // 0..28
#pragma unroll
            for (int i = 0; i < 4; i++) {
                int r = rl + 4 * i;
                float4 v = *(float4*)&s_stage[r * STG_PITCH + cl];
                int tg = t0 + wm * 16 + r;
                *(float4*)&attn_out[((size_t)bh * TT + tg) * SS + c0 + wn * 32 + cl] = v;
            }
            __syncwarp();
        }

        // O += P @ V over this warp's own 32 k-columns (A-frags via shuffles)
#pragma unroll
        for (int j = 0; j < 4; j++) {
            float u0 = __shfl_sync(0xffffffffu, acc[j][0], srcA);
            float u1 = __shfl_sync(0xffffffffu, acc[j][1], srcA);
            float v0 = __shfl_sync(0xffffffffu, acc[j][2], srcA);
            float v1 = __shfl_sync(0xffffffffu, acc[j][3], srcA);
            float w0 = __shfl_sync(0xffffffffu, acc[j][0], srcA + 2);
            float w1 = __shfl_sync(0xffffffffu, acc[j][1], srcA + 2);
            float x0 = __shfl_sync(0xffffffffu, acc[j][2], srcA + 2);
            float x1 = __shfl_sync(0xffffffffu, acc[j][3], srcA + 2);
            uint32_t af[4];
            af[0] = __float_as_uint(oddp ? u1 : u0);
            af[1] = __float_as_uint(oddp ? v1 : v0);
            af[2] = __float_as_uint(oddp ? w1 : w0);
            af[3] = __float_as_uint(oddp ? x1 : x0);

            uint32_t kc = (uint32_t)((wn * 4 + j) * 2 + klane);
#pragma unroll
            for (int nt = 0; nt < 4; nt++) {
                int br = nt * 16 + lrow;
                uint32_t bf[4];
                ldsm4(bf, vb + br * 256 + ((kc ^ (uint32_t)(br & 7)) << 4));
                mma_tf32(oacc[2 * nt],     af, bf[0], bf[2]);
                mma_tf32(oacc[2 * nt + 1], af, bf[1], bf[3]);
            }
        }
        __syncthreads();   // K/V reads done before buffers refilled

        if (it + 2 < 16) {
            prefetch_kv(it + 2);
            CP_COMMIT();
        }
    }

    // row-sum reduction: quad shuffle, then 2-way cross-warp via smem
    rs0 += __shfl_xor_sync(0xffffffffu, rs0, 1);
    rs0 += __shfl_xor_sync(0xffffffffu, rs0, 2);
    rs1 += __shfl_xor_sync(0xffffffffu, rs1, 1);
    rs1 += __shfl_xor_sync(0xffffffffu, rs1, 2);
    if ((lane & 3) == 0) {
        s_part[wn * 64 + r0] = rs0;
        s_part[wn * 64 + r1] = rs1;
    }
    // k-split partials: wn==1 stores O partial to s_red (reuses K buffer)
    if (wn == 1) {
#pragma unroll
        for (int n8 = 0; n8 < 8; n8++) {
            int cc = n8 * 8 + cbase;
            *(float2*)&s_red[r0 * RED_PITCH + cc] = *(float2*)&oacc[n8][0];
            *(float2*)&s_red[r1 * RED_PITCH + cc] = *(float2*)&oacc[n8][2];
        }
    }
    if (attn_out) asm volatile("membar.cta;" ::: "memory");
    __syncthreads();
    if (tid < 64) {
        s_sum[tid] = 1.f / (s_part[tid] + s_part[64 + tid]);
    }
    __syncthreads();

    // wn==0 warps: combine k-split partials, scale, write P gmem (tf32)
    if (wn == 0) {
        float inv0 = s_sum[r0], inv1 = s_sum[r1];
#pragma unroll
        for (int n8 = 0; n8 < 8; n8++) {
            int cc = n8 * 8 + cbase;
            float2 q0 = *(float2*)&s_red[r0 * RED_PITCH + cc];
            float2 q1 = *(float2*)&s_red[r1 * RED_PITCH + cc];
            float2 v0 = {tf32r((oacc[n8][0] + q0.x) * inv0), tf32r((oacc[n8][1] + q0.y) * inv0)};
            float2 v1 = {tf32r((oacc[n8][2] + q1.x) * inv1), tf32r((oacc[n8][3] + q1.y) * inv1)};
            *(float2*)&P[((size_t)(t0 + r0) * BX + b) * EE + h * DH + cc] = v0;
            *(float2*)&P[((size_t)(t0 + r1) * BX + b) * EE + h * DH + cc] = v1;
        }
    }

    // rescale this block's attn rows (unnormalized -> probabilities)
    if (attn_out) {
        const int r = tid >> 2;
        const int l4 = tid & 3;
        const float inv = s_sum[r];
        float* row = attn_out + ((size_t)bh * TT + t0 + r) * SS;
#pragma unroll 8
        for (int i = 0; i < 64; i++) {
            float4 v = *(float4*)&row[l4 * 4 + i * 16];
            v.x *= inv; v.y *= inv; v.z *= inv; v.w *= inv;
            *(float4*)&row[l4 * 4 + i * 16] = v;
        }
    }
}

// ---------------------------------------------------------------------------
// Launch
// ---------------------------------------------------------------------------
extern "C" void kernel_launch(void* const* d_in, const int* in_sizes, int n_in,
                              void* d_out, int out_size)
{
    const float* src   = (const float*)d_in[0];
    const float* tgt   = (const float*)d_in[1];
    const float* spad  = (const float*)d_in[2];
    const float* tpad  = (const float*)d_in[3];
    const float* amask = (const float*)d_in[4];
    const int*   caus  = (const int*)  d_in[5];
    const float* Wq    = (const float*)d_in[6];
    const float* Wk    = (const float*)d_in[7];
    const float* Wv    = (const float*)d_in[8];
    const float* Wo    = (const float*)d_in[9];
    const float* bo    = (const float*)d_in[10];

    const size_t OUT_N  = (size_t)TT * BX * EE;
    const size_t ATTN_N = (size_t)BX * HH * TT * SS;

    float* out_p  = nullptr;
    float* attn_p = nullptr;
    if ((size_t)out_size == OUT_N + ATTN_N) {
        out_p  = (float*)d_out;
        attn_p = (float*)d_out + OUT_N;
    } else if ((size_t)out_size == ATTN_N) {
        attn_p = (float*)d_out;
    } else {
        out_p  = (float*)d_out;
    }

    float *Qp, *Kp, *Vtp, *Pp, *Wtp, *Arp, *Brp;
    cudaGetSymbolAddress((void**)&Qp, g_Q);
    cudaGetSymbolAddress((void**)&Kp, g_K);
    cudaGetSymbolAddress((void**)&Vtp, g_Vt);
    cudaGetSymbolAddress((void**)&Pp, g_P);
    cudaGetSymbolAddress((void**)&Wtp, g_Wt);
    cudaGetSymbolAddress((void**)&Arp, g_Ar);
    cudaGetSymbolAddress((void**)&Brp, g_Br);

    const int ATTN_SMEM = ATTN2_FLOATS * (int)sizeof(float);
    cudaFuncSetAttribute(attn_kernel, cudaFuncAttributeMaxDynamicSharedMemorySize, ATTN_SMEM);
    cudaFuncSetAttribute(gemm_qkv_kernel, cudaFuncAttributeMaxDynamicSharedMemorySize, GSMEM);
    cudaFuncSetAttribute(gemm_out_kernel, cudaFuncAttributeMaxDynamicSharedMemorySize, GSMEM);

    // pre-round inputs + transpose weights
    round_tf32_kernel<<<dim3(512, 1, 2), 256>>>(tgt, src, Arp, Brp);
    transpose_tf32_kernel<<<dim3(32, 32, 4), 256>>>(Wq, Wk, Wv, Wo, Wtp);

    // merged QKV projections (2 CTAs/SM)
    gemm_qkv_kernel<<<dim3(8, 32, 3), 256, GSMEM>>>(Arp, Brp, Wtp, Qp, Kp, Vtp);

    // fused attention (2 CTAs/SM)
    dim3 agrid(TT / AT2, BX * HH);   // (16, 64)
    attn_kernel<<<agrid, dim3(256), ATTN_SMEM>>>(Qp, Kp, Vtp, tpad, spad, amask,
                                                 caus, attn_p, Pp);

    // output projection (2 CTAs/SM)
    if (out_p) {
        gemm_out_kernel<<<dim3(8, 32), 256, GSMEM>>>(Pp, Wtp + 3 * (size_t)EE * EE, bo, out_p);
    }
}

// round 14
// speedup vs baseline: 1.5331x; 1.5175x over previous
#include <cuda_runtime.h>
#include <cuda_fp16.h>
#include <math.h>
#include <cstdint>

// Problem constants
#define BX   4
#define TT   1024
#define SS   1024
#define EE   1024
#define HH   16
#define DH   64

// Scratch (device globals; no allocation allowed) — fp16 tensor path
__device__ __half g_Q[BX * HH * TT * DH];   // [B,H,T,D]  fp16, pre-scaled by 1/8
__device__ __half g_K[BX * HH * SS * DH];   // [B,H,S,D]  fp16
__device__ __half g_Vt[BX * HH * DH * SS];  // [B,H,D,S]  fp16
__device__ __half g_P[TT * BX * EE];        // [T,B,E]    fp16
__device__ __half g_Wt[4 * EE * EE];        // W^T [N,K]  fp16
__device__ __half g_Ar[BX * TT * EE];       // tgt fp16
__device__ __half g_Br[BX * SS * EE];       // src fp16

// ---------------------------------------------------------------------------
// Helpers
// ---------------------------------------------------------------------------
__device__ __forceinline__ uint32_t smem_u32(const void* p) {
    uint32_t a;
    asm("{ .reg .u64 t; cvta.to.shared.u64 t, %1; cvt.u32.u64 %0, t; }" : "=r"(a) : "l"(p));
    return a;
}
__device__ __forceinline__ uint32_t pack_h2(float a, float b) {
    __half2 h = __floats2half2_rn(a, b);
    return *(uint32_t*)&h;
}

__device__ __forceinline__ void cp16(uint32_t dst, const void* src) {
    asm volatile("cp.async.cg.shared.global [%0], [%1], 16;" :: "r"(dst), "l"(src));
}
#define CP_COMMIT() asm volatile("cp.async.commit_group;" ::: "memory")
#define CP_WAIT1()  asm volatile("cp.async.wait_group 1;" ::: "memory")

__device__ __forceinline__ void ldsm4(uint32_t* r, uint32_t addr) {
    asm volatile("ldmatrix.sync.aligned.m8n8.x4.shared.b16 {%0,%1,%2,%3}, [%4];"
                 : "=r"(r[0]), "=r"(r[1]), "=r"(r[2]), "=r"(r[3]) : "r"(addr));
}
// fp16 MMA: D(f32) += A(f16) * B(f16), m16n8k16
__device__ __forceinline__ void mma_f16(float* d, const uint32_t* a, uint32_t b0, uint32_t b1) {
    asm volatile("mma.sync.aligned.m16n8k16.row.col.f32.f16.f16.f32 "
                 "{%0,%1,%2,%3}, {%4,%5,%6,%7}, {%8,%9}, {%0,%1,%2,%3};"
                 : "+f"(d[0]), "+f"(d[1]), "+f"(d[2]), "+f"(d[3])
                 : "r"(a[0]), "r"(a[1]), "r"(a[2]), "r"(a[3]), "r"(b0), "r"(b1));
}

// ---------------------------------------------------------------------------
// fp32 -> fp16 rounding copies (z selects tensor)
// ---------------------------------------------------------------------------
__global__ __launch_bounds__(256)
void round_f16_kernel(const float* __restrict__ a, const float* __restrict__ b,
                      __half* __restrict__ oa, __half* __restrict__ ob)
{
    const float* src = blockIdx.z ? b : a;
    __half* dst = blockIdx.z ? ob : oa;
    const int n4 = (BX * TT * EE) / 4;
    for (int i = blockIdx.x * 256 + threadIdx.x; i < n4; i += gridDim.x * 256) {
        float4 v = ((const float4*)src)[i];
        uint2 o;
        o.x = pack_h2(v.x, v.y);
        o.y = pack_h2(v.z, v.w);
        ((uint2*)dst)[i] = o;
    }
}

// ---------------------------------------------------------------------------
// Weight transpose + fp16 round, 4 weights in one launch (z selects)
// ---------------------------------------------------------------------------
__global__ __launch_bounds__(256)
void transpose_f16_kernel(const float* __restrict__ W0, const float* __restrict__ W1,
                          const float* __restrict__ W2, const float* __restrict__ W3,
                          __half* __restrict__ WtBase)
{
    __shared__ float tile[32][33];
    const int z = blockIdx.z;
    const float* W = (z == 0) ? W0 : (z == 1) ? W1 : (z == 2) ? W2 : W3;
    __half* Wt = WtBase + (size_t)z * EE * EE;
    const int k0 = blockIdx.y * 32, n0 = blockIdx.x * 32;
    const int tx = threadIdx.x & 31, ty = threadIdx.x >> 5;
#pragma unroll
    for (int t = 0; t < 4; t++)
        tile[ty + 8 * t][tx] = W[(size_t)(k0 + ty + 8 * t) * EE + n0 + tx];
    __syncthreads();
#pragma unroll
    for (int t = 0; t < 4; t++)
        Wt[(size_t)(n0 + ty + 8 * t) * EE + k0 + tx] = __float2half_rn(tile[tx][ty + 8 * t]);
}

// ---------------------------------------------------------------------------
// fp16 mma.sync GEMM: C[4096,1024] = A[4096,1024] @ Wt[1024(N),1024(K)]^T
// Tile 128x128, k-tile 64 (16 iters), 3-stage cp.async, 2 CTAs/SM.
// Tiles: 128 rows x 64 fp16 = 128B rows, XOR-swizzled 16B chunks.
// mode 0: fp32 out + bias; mode 1: fp16 scatter [B,H,L,D] (*scale);
// mode 2: fp16 scatter [B,H,D,S]^T
// ---------------------------------------------------------------------------
#define GSMEM (3 * 32768 + 1024)

__device__ __forceinline__ void gemm_body(
    const __half* __restrict__ A, const __half* __restrict__ Bt,
    const float* __restrict__ bias, void* __restrict__ Cv,
    int mode, float scale, int L)
{
    extern __shared__ char dyn_sm[];
    char* sm = (char*)(((uintptr_t)dyn_sm + 1023) & ~(uintptr_t)1023);
    const uint32_t sb = smem_u32(sm);

    const int tid  = threadIdx.x;
    const int wid  = tid >> 5;
    const int lane = tid & 31;
    const int wm   = wid & 3;
    const int wn   = wid >> 2;
    const int m0 = blockIdx.y * 128;
    const int n0 = blockIdx.x * 128;

    const __half* Ap = A  + (size_t)m0 * 1024;
    const __half* Bp = Bt + (size_t)n0 * 1024;

    const int lrow16 = lane & 15;
    const int kh16   = lane >> 4;

    float acc[2][8][4];
#pragma unroll
    for (int mt = 0; mt < 2; mt++)
#pragma unroll
        for (int nt = 0; nt < 8; nt++)
#pragma unroll
            for (int c = 0; c < 4; c++) acc[mt][nt][c] = 0.f;

    auto prefetch = [&](int st, int kt) {
        const int k0 = kt * 64;
        const uint32_t ao = sb + st * 32768;
        const uint32_t bo = ao + 16384;
#pragma unroll
        for (int t = 0; t < 4; t++) {
            int idx = tid + t * 256;
            int r = idx >> 3, c = idx & 7;
            uint32_t sw = (uint32_t)(r * 128 + ((c ^ (r & 7)) << 4));
            cp16(ao + sw, Ap + (size_t)r * 1024 + k0 + c * 8);
            cp16(bo + sw, Bp + (size_t)r * 1024 + k0 + c * 8);
        }
    };

    prefetch(0, 0); CP_COMMIT();
    prefetch(1, 1); CP_COMMIT();

#pragma unroll 1
    for (int kt = 0; kt < 16; kt++) {
        CP_WAIT1();
        __syncthreads();
        if (kt + 2 < 16) prefetch((kt + 2) % 3, kt + 2);
        CP_COMMIT();

        const uint32_t ab = sb + (kt % 3) * 32768;
        const uint32_t bb = ab + 16384;
#pragma unroll
        for (int k16 = 0; k16 < 4; k16++) {
            const uint32_t kc = (uint32_t)(k16 * 2 + kh16);
            uint32_t af[2][4], bf[4][4];
#pragma unroll
            for (int mt = 0; mt < 2; mt++) {
                int r = wm * 32 + mt * 16 + lrow16;
                ldsm4(af[mt], ab + r * 128 + ((kc ^ (uint32_t)(r & 7)) << 4));
            }
#pragma unroll
            for (int g = 0; g < 4; g++) {
                int r = wn * 64 + g * 16 + lrow16;
                ldsm4(bf[g], bb + r * 128 + ((kc ^ (uint32_t)(r & 7)) << 4));
            }
#pragma unroll
            for (int mt = 0; mt < 2; mt++)
#pragma unroll
                for (int g = 0; g < 4; g++) {
                    mma_f16(acc[mt][2 * g],     af[mt], bf[g][0], bf[g][2]);
                    mma_f16(acc[mt][2 * g + 1], af[mt], bf[g][1], bf[g][3]);
                }
        }
    }

    const int rbase = lane >> 2;
    const int cbase = 2 * (lane & 3);
#pragma unroll
    for (int mt = 0; mt < 2; mt++) {
#pragma unroll
        for (int nt = 0; nt < 8; nt++) {
            int n = n0 + wn * 64 + nt * 8 + cbase;
#pragma unroll
            for (int half_ = 0; half_ < 2; half_++) {
                int m = m0 + wm * 32 + mt * 16 + rbase + half_ * 8;
                float vx = acc[mt][nt][half_ * 2 + 0];
                float vy = acc[mt][nt][half_ * 2 + 1];
                if (mode == 0) {
                    float2 v = {vx + bias[n], vy + bias[n + 1]};
                    *(float2*)&((float*)Cv)[(size_t)m * 1024 + n] = v;
                } else if (mode == 1) {
                    int b = m / L, l = m % L;
                    size_t o = (((size_t)(b * HH + (n >> 6)) * L + l) * DH) + (n & 63);
                    uint32_t h = pack_h2(vx * scale, vy * scale);
                    *(uint32_t*)&((__half*)Cv)[o] = h;
                } else {
                    int b = m / L, s = m % L;
                    size_t o = (((size_t)(b * HH + (n >> 6)) * DH) + (n & 63)) * (size_t)L + s;
                    ((__half*)Cv)[o]     = __float2half_rn(vx);
                    ((__half*)Cv)[o + L] = __float2half_rn(vy);
                }
            }
        }
    }
}

__global__ __launch_bounds__(256, 2)
void gemm_qkv_kernel(const __half* __restrict__ Atgt, const __half* __restrict__ Asrc,
                     const __half* __restrict__ Wt,
                     __half* __restrict__ Cq, __half* __restrict__ Ck, __half* __restrict__ Cvt)
{
    const int z = blockIdx.z;
    const __half* A = (z == 0) ? Atgt : Asrc;
    const __half* W = Wt + (size_t)z * EE * EE;
    __half* C = (z == 0) ? Cq : (z == 1) ? Ck : Cvt;
    gemm_body(A, W, nullptr, C, (z == 2) ? 2 : 1, (z == 0) ? 0.125f : 1.0f, (z == 0) ? TT : SS);
}

__global__ __launch_bounds__(256, 2)
void gemm_out_kernel(const __half* __restrict__ A, const __half* __restrict__ Wt,
                     const float* __restrict__ bias, float* __restrict__ C)
{
    gemm_body(A, Wt, bias, C, 0, 1.0f, TT);
}

// ---------------------------------------------------------------------------
// Fused flash-style attention, fp16 tensor path (R10 pipeline structure).
// 256 threads, 2 CTAs/SM, 64 t-rows/block, 16 iters of 64-col tiles.
// m16n8k16 MMAs; PV A-frags built from exp registers by half2 packing
// (no smem P, no shuffles). PV k-split 2, reduced at end.
// ---------------------------------------------------------------------------
#define AT2 64
// byte offsets
#define B_Q    0                    // 64x64 fp16, 128B rows swizzled   8192
#define B_K    8192                 // 2 x 8192                        16384
#define B_V    24576                // 2 x 8192                        16384
#define B_SP   40960                // spad (fp32) 1024 floats          4096
#define B_PART 45056                // 128 floats                        512
#define B_SUM  45568                // 64 floats                         256
#define ATTN_BYTES 45824
#define RED_PITCH 72                // k-split O reduce (floats), reuses K/V region

__global__ __launch_bounds__(256, 2)
void attn_kernel(const __half* __restrict__ Q, const __half* __restrict__ K,
                 const __half* __restrict__ Vt,
                 const float* __restrict__ tpad, const float* __restrict__ spad,
                 const float* __restrict__ amask, const int* __restrict__ causal_p,
                 float* __restrict__ attn_out, __half* __restrict__ P)
{
    extern __shared__ float smf[];
    const uint32_t base = smem_u32(smf);
    const uint32_t q_b  = base + B_Q;
    const uint32_t k_b  = base + B_K;
    const uint32_t v_b  = base + B_V;
    const uint32_t sp_b = base + B_SP;
    float* s_sp   = smf + B_SP / 4;
    float* s_part = smf + B_PART / 4;
    float* s_sum  = smf + B_SUM / 4;
    float* s_red  = smf + B_K / 4;   // reused after main loop (barrier-guarded)

    const int tid = threadIdx.x;
    const int bh  = blockIdx.y;
    const int b   = bh >> 4;
    const int h   = bh & 15;
    const int t0  = blockIdx.x * AT2;
    const bool causal = (causal_p[0] != 0);

    const size_t qbase  = ((size_t)bh * TT + t0) * DH;
    const size_t kbase  = (size_t)bh * SS * DH;
    const size_t vtbase = (size_t)bh * DH * SS;

    const int lane  = tid & 31;
    const int wid   = tid >> 5;
    const int wm    = wid & 3;    // m16 group
    const int wn    = wid >> 2;   // n32 group (0/1); also PV k-split id
    const int lrow16 = lane & 15;
    const int kh16   = lane >> 4;
    const int rbase = lane >> 2;
    const int cbase = 2 * (lane & 3);

    const int r0 = wm * 16 + rbase;
    const int r1 = r0 + 8;
    const float tm0 = tpad[b * TT + t0 + r0];
    const float tm1 = tpad[b * TT + t0 + r1];

    auto prefetch_kv = [&](int it) {
        const uint32_t kb = k_b + (uint32_t)(it & 1) * 8192;
        const uint32_t vb = v_b + (uint32_t)(it & 1) * 8192;
        const int c0 = it * 64;
#pragma unroll
        for (int t = 0; t < 2; t++) {
            int idx = tid + t * 256;
            int r = idx >> 3, c = idx & 7;
            uint32_t sw = (uint32_t)(r * 128 + ((c ^ (r & 7)) << 4));
            cp16(kb + sw, K + kbase + (size_t)(c0 + r) * DH + c * 8);
            cp16(vb + sw, Vt + vtbase + (size_t)r * SS + c0 + c * 8);
        }
    };

    // prologue: [Q + spad + KV0] , [KV1]
    {
#pragma unroll
        for (int t = 0; t < 2; t++) {
            int idx = tid + t * 256;
            int r = idx >> 3, c = idx & 7;
            cp16(q_b + r * 128 + ((c ^ (r & 7)) << 4), Q + qbase + (size_t)r * DH + c * 8);
        }
        cp16(sp_b + tid * 16, spad + b * SS + tid * 4);
    }
    prefetch_kv(0);
    CP_COMMIT();
    prefetch_kv(1);
    CP_COMMIT();

    CP_WAIT1();
    __syncthreads();

    // preload Q fragments: m16 x k64 = 4 ldsm.x4
    uint32_t qf[4][4];
#pragma unroll
    for (int k16 = 0; k16 < 4; k16++) {
        int r = wm * 16 + lrow16;
        uint32_t kc = (uint32_t)(k16 * 2 + kh16);
        ldsm4(qf[k16], q_b + r * 128 + ((kc ^ (uint32_t)(r & 7)) << 4));
    }

    float rs0 = 0.f, rs1 = 0.f;
    float oacc[8][4];                        // m16 x n64 partial (own k slice)
#pragma unroll
    for (int n8 = 0; n8 < 8; n8++)
#pragma unroll
        for (int c = 0; c < 4; c++) oacc[n8][c] = 0.f;

#pragma unroll 1
    for (int it = 0; it < 16; it++) {
        if (it > 0) {
            CP_WAIT1();
            __syncthreads();
        }
        const int c0 = it * 64;
        const uint32_t kb = k_b + (uint32_t)(it & 1) * 8192;
        const uint32_t vb = v_b + (uint32_t)(it & 1) * 8192;

        // mask loads early
        float2 am[4][2];
#pragma unroll
        for (int n8 = 0; n8 < 4; n8++) {
            int sc = c0 + wn * 32 + n8 * 8 + cbase;
            am[n8][0] = *(const float2*)&amask[((size_t)b * TT + t0 + r0) * SS + sc];
            am[n8][1] = *(const float2*)&amask[((size_t)b * TT + t0 + r1) * SS + sc];
        }

        // S = Q @ K^T  (warp m16 x n32, k = 64 via 4 k16 steps)
        float acc[4][4];
#pragma unroll
        for (int n8 = 0; n8 < 4; n8++)
#pragma unroll
            for (int c = 0; c < 4; c++) acc[n8][c] = 0.f;

#pragma unroll
        for (int k16 = 0; k16 < 4; k16++) {
            uint32_t kc = (uint32_t)(k16 * 2 + kh16);
#pragma unroll
            for (int ng = 0; ng < 2; ng++) {
                int r = wn * 32 + ng * 16 + lrow16;
                uint32_t bf[4];
                ldsm4(bf, kb + r * 128 + ((kc ^ (uint32_t)(r & 7)) << 4));
                mma_f16(acc[2 * ng],     qf[k16], bf[0], bf[2]);
                mma_f16(acc[2 * ng + 1], qf[k16], bf[1], bf[3]);
            }
        }

        // exp (no max shift), attn write (unnormalized fp32), row sums
        const int tg0 = t0 + r0, tg1 = t0 + r1;
#pragma unroll
        for (int n8 = 0; n8 < 4; n8++) {
            int scl = wn * 32 + n8 * 8 + cbase;
            int sc  = c0 + scl;
            float2 sp = *(const float2*)&s_sp[sc];

            float m00 = tm0 * sp.x * am[n8][0].x;
            float m01 = tm0 * sp.y * am[n8][0].y;
            float m10 = tm1 * sp.x * am[n8][1].x;
            float m11 = tm1 * sp.y * am[n8][1].y;
            if (causal) {
                if (sc > tg0)     m00 = 0.f;
                if (sc + 1 > tg0) m01 = 0.f;
                if (sc > tg1)     m10 = 0.f;
                if (sc + 1 > tg1) m11 = 0.f;
            }
            float e00 = __expf(acc[n8][0] + m00);
            float e01 = __expf(acc[n8][1] + m01);
            float e10 = __expf(acc[n8][2] + m10);
            float e11 = __expf(acc[n8][3] + m11);
            rs0 += e00 + e01;
            rs1 += e10 + e11;

            if (attn_out) {
                float2 w0 = {e00, e01}, w1 = {e10, e11};
                *(float2*)&attn_out[((size_t)bh * TT + tg0) * SS + sc] = w0;
                *(float2*)&attn_out[((size_t)bh * TT + tg1) * SS + sc] = w1;
            }
            acc[n8][0] = e00; acc[n8][1] = e01;
            acc[n8][2] = e10; acc[n8][3] = e11;
        }

        // O += P @ V over this warp's own 32 k-cols (2 k16 chunks).
        // A-frags come straight from exp registers: a0=(q,2p:2p+1) of tile j0,
        // a1=(q+8,..) of j0, a2/a3 = same of tile j1 (k+8). No shuffles.
#pragma unroll
        for (int kp = 0; kp < 2; kp++) {
            int j0 = 2 * kp, j1 = 2 * kp + 1;
            uint32_t af[4];
            af[0] = pack_h2(acc[j0][0], acc[j0][1]);
            af[1] = pack_h2(acc[j0][2], acc[j0][3]);
            af[2] = pack_h2(acc[j1][0], acc[j1][1]);
            af[3] = pack_h2(acc[j1][2], acc[j1][3]);

            uint32_t kc = (uint32_t)((wn * 2 + kp) * 2 + kh16);
#pragma unroll
            for (int nt = 0; nt < 4; nt++) {
                int r = nt * 16 + lrow16;
                uint32_t bf[4];
                ldsm4(bf, vb + r * 128 + ((kc ^ (uint32_t)(r & 7)) << 4));
                mma_f16(oacc[2 * nt],     af, bf[0], bf[2]);
                mma_f16(oacc[2 * nt + 1], af, bf[1], bf[3]);
            }
        }
        __syncthreads();   // K/V reads done before buffers refilled

        if (it + 2 < 16) {
            prefetch_kv(it + 2);
            CP_COMMIT();
        }
    }

    // row-sum reduction: quad shuffle, then 2-way cross-warp via smem
    rs0 += __shfl_xor_sync(0xffffffffu, rs0, 1);
    rs0 += __shfl_xor_sync(0xffffffffu, rs0, 2);
    rs1 += __shfl_xor_sync(0xffffffffu, rs1, 1);
    rs1 += __shfl_xor_sync(0xffffffffu, rs1, 2);
    if ((lane & 3) == 0) {
        s_part[wn * 64 + r0] = rs0;
        s_part[wn * 64 + r1] = rs1;
    }
    // k-split partials: wn==1 stores O partial to s_red (reuses K/V region)
    if (wn == 1) {
#pragma unroll
        for (int n8 = 0; n8 < 8; n8++) {
            int cc = n8 * 8 + cbase;
            *(float2*)&s_red[r0 * RED_PITCH + cc] = *(float2*)&oacc[n8][0];
            *(float2*)&s_red[r1 * RED_PITCH + cc] = *(float2*)&oacc[n8][2];
        }
    }
    if (attn_out) asm volatile("membar.cta;" ::: "memory");
    __syncthreads();
    if (tid < 64) {
        s_sum[tid] = 1.f / (s_part[tid] + s_part[64 + tid]);
    }
    __syncthreads();

    // wn==0 warps: combine k-split partials, scale, write P gmem (fp16)
    if (wn == 0) {
        float inv0 = s_sum[r0], inv1 = s_sum[r1];
#pragma unroll
        for (int n8 = 0; n8 < 8; n8++) {
            int cc = n8 * 8 + cbase;
            float2 q0 = *(float2*)&s_red[r0 * RED_PITCH + cc];
            float2 q1 = *(float2*)&s_red[r1 * RED_PITCH + cc];
            uint32_t h0 = pack_h2((oacc[n8][0] + q0.x) * inv0, (oacc[n8][1] + q0.y) * inv0);
            uint32_t h1 = pack_h2((oacc[n8][2] + q1.x) * inv1, (oacc[n8][3] + q1.y) * inv1);
            *(uint32_t*)&P[((size_t)(t0 + r0) * BX + b) * EE + h * DH + cc] = h0;
            *(uint32_t*)&P[((size_t)(t0 + r1) * BX + b) * EE + h * DH + cc] = h1;
        }
    }

    // rescale this block's attn rows (unnormalized -> probabilities)
    if (attn_out) {
        const int r = tid >> 2;
        const int l4 = tid & 3;
        const float inv = s_sum[r];
        float* row = attn_out + ((size_t)bh * TT + t0 + r) * SS;
#pragma unroll 8
        for (int i = 0; i < 64; i++) {
            float4 v = *(float4*)&row[l4 * 4 + i * 16];
            v.x *= inv; v.y *= inv; v.z *= inv; v.w *= inv;
            *(float4*)&row[l4 * 4 + i * 16] = v;
        }
    }
}

// ---------------------------------------------------------------------------
// Launch
// ---------------------------------------------------------------------------
extern "C" void kernel_launch(void* const* d_in, const int* in_sizes, int n_in,
                              void* d_out, int out_size)
{
    const float* src   = (const float*)d_in[0];
    const float* tgt   = (const float*)d_in[1];
    const float* spad  = (const float*)d_in[2];
    const float* tpad  = (const float*)d_in[3];
    const float* amask = (const float*)d_in[4];
    const int*   caus  = (const int*)  d_in[5];
    const float* Wq    = (const float*)d_in[6];
    const float* Wk    = (const float*)d_in[7];
    const float* Wv    = (const float*)d_in[8];
    const float* Wo    = (const float*)d_in[9];
    const float* bo    = (const float*)d_in[10];

    const size_t OUT_N  = (size_t)TT * BX * EE;
    const size_t ATTN_N = (size_t)BX * HH * TT * SS;

    float* out_p  = nullptr;
    float* attn_p = nullptr;
    if ((size_t)out_size == OUT_N + ATTN_N) {
        out_p  = (float*)d_out;
        attn_p = (float*)d_out + OUT_N;
    } else if ((size_t)out_size == ATTN_N) {
        attn_p = (float*)d_out;
    } else {
        out_p  = (float*)d_out;
    }

    __half *Qp, *Kp, *Vtp, *Pp, *Wtp, *Arp, *Brp;
    cudaGetSymbolAddress((void**)&Qp, g_Q);
    cudaGetSymbolAddress((void**)&Kp, g_K);
    cudaGetSymbolAddress((void**)&Vtp, g_Vt);
    cudaGetSymbolAddress((void**)&Pp, g_P);
    cudaGetSymbolAddress((void**)&Wtp, g_Wt);
    cudaGetSymbolAddress((void**)&Arp, g_Ar);
    cudaGetSymbolAddress((void**)&Brp, g_Br);

    cudaFuncSetAttribute(attn_kernel, cudaFuncAttributeMaxDynamicSharedMemorySize, ATTN_BYTES);
    cudaFuncSetAttribute(gemm_qkv_kernel, cudaFuncAttributeMaxDynamicSharedMemorySize, GSMEM);
    cudaFuncSetAttribute(gemm_out_kernel, cudaFuncAttributeMaxDynamicSharedMemorySize, GSMEM);

    // pre-round inputs + transpose weights (fp16)
    round_f16_kernel<<<dim3(512, 1, 2), 256>>>(tgt, src, Arp, Brp);
    transpose_f16_kernel<<<dim3(32, 32, 4), 256>>>(Wq, Wk, Wv, Wo, Wtp);

    // merged QKV projections (2 CTAs/SM)
    gemm_qkv_kernel<<<dim3(8, 32, 3), 256, GSMEM>>>(Arp, Brp, Wtp, Qp, Kp, Vtp);

    // fused attention (2 CTAs/SM)
    dim3 agrid(TT / AT2, BX * HH);   // (16, 64)
    attn_kernel<<<agrid, dim3(256), ATTN_BYTES>>>(Qp, Kp, Vtp, tpad, spad, amask,
                                                  caus, attn_p, Pp);

    // output projection (2 CTAs/SM)
    if (out_p) {
        gemm_out_kernel<<<dim3(8, 32), 256, GSMEM>>>(Pp, Wtp + 3 * (size_t)EE * EE, bo, out_p);
    }
}

// round 15
// speedup vs baseline: 1.6065x; 1.0478x over previous
#include <cuda_runtime.h>
#include <cuda_fp16.h>
#include <math.h>
#include <cstdint>

// Problem constants
#define BX   4
#define TT   1024
#define SS   1024
#define EE   1024
#define HH   16
#define DH   64

// Scratch (device globals; no allocation allowed) — fp16 tensor path
__device__ __half g_Q[BX * HH * TT * DH];   // [B,H,T,D]  fp16, pre-scaled by 1/8
__device__ __half g_K[BX * HH * SS * DH];   // [B,H,S,D]  fp16
__device__ __half g_Vt[BX * HH * DH * SS];  // [B,H,D,S]  fp16
__device__ __half g_P[TT * BX * EE];        // [T,B,E]    fp16
__device__ __half g_Wt[4 * EE * EE];        // W^T [N,K]  fp16
__device__ __half g_Ar[BX * TT * EE];       // tgt fp16
__device__ __half g_Br[BX * SS * EE];       // src fp16

// ---------------------------------------------------------------------------
// Helpers
// ---------------------------------------------------------------------------
__device__ __forceinline__ uint32_t smem_u32(const void* p) {
    uint32_t a;
    asm("{ .reg .u64 t; cvta.to.shared.u64 t, %1; cvt.u32.u64 %0, t; }" : "=r"(a) : "l"(p));
    return a;
}
__device__ __forceinline__ uint32_t pack_h2(float a, float b) {
    __half2 h = __floats2half2_rn(a, b);
    return *(uint32_t*)&h;
}

__device__ __forceinline__ void cp16(uint32_t dst, const void* src) {
    asm volatile("cp.async.cg.shared.global [%0], [%1], 16;" :: "r"(dst), "l"(src));
}
#define CP_COMMIT() asm volatile("cp.async.commit_group;" ::: "memory")
#define CP_WAIT1()  asm volatile("cp.async.wait_group 1;" ::: "memory")

__device__ __forceinline__ void ldsm4(uint32_t* r, uint32_t addr) {
    asm volatile("ldmatrix.sync.aligned.m8n8.x4.shared.b16 {%0,%1,%2,%3}, [%4];"
                 : "=r"(r[0]), "=r"(r[1]), "=r"(r[2]), "=r"(r[3]) : "r"(addr));
}
// fp16 MMA: D(f32) += A(f16) * B(f16), m16n8k16
__device__ __forceinline__ void mma_f16(float* d, const uint32_t* a, uint32_t b0, uint32_t b1) {
    asm volatile("mma.sync.aligned.m16n8k16.row.col.f32.f16.f16.f32 "
                 "{%0,%1,%2,%3}, {%4,%5,%6,%7}, {%8,%9}, {%0,%1,%2,%3};"
                 : "+f"(d[0]), "+f"(d[1]), "+f"(d[2]), "+f"(d[3])
                 : "r"(a[0]), "r"(a[1]), "r"(a[2]), "r"(a[3]), "r"(b0), "r"(b1));
}

// ---------------------------------------------------------------------------
// fp32 -> fp16 rounding copies (z selects tensor)
// ---------------------------------------------------------------------------
__global__ __launch_bounds__(256)
void round_f16_kernel(const float* __restrict__ a, const float* __restrict__ b,
                      __half* __restrict__ oa, __half* __restrict__ ob)
{
    const float* src = blockIdx.z ? b : a;
    __half* dst = blockIdx.z ? ob : oa;
    const int n4 = (BX * TT * EE) / 4;
    for (int i = blockIdx.x * 256 + threadIdx.x; i < n4; i += gridDim.x * 256) {
        float4 v = ((const float4*)src)[i];
        uint2 o;
        o.x = pack_h2(v.x, v.y);
        o.y = pack_h2(v.z, v.w);
        ((uint2*)dst)[i] = o;
    }
}

// ---------------------------------------------------------------------------
// Weight transpose + fp16 round, 4 weights in one launch (z selects)
// ---------------------------------------------------------------------------
__global__ __launch_bounds__(256)
void transpose_f16_kernel(const float* __restrict__ W0, const float* __restrict__ W1,
                          const float* __restrict__ W2, const float* __restrict__ W3,
                          __half* __restrict__ WtBase)
{
    __shared__ float tile[32][33];
    const int z = blockIdx.z;
    const float* W = (z == 0) ? W0 : (z == 1) ? W1 : (z == 2) ? W2 : W3;
    __half* Wt = WtBase + (size_t)z * EE * EE;
    const int k0 = blockIdx.y * 32, n0 = blockIdx.x * 32;
    const int tx = threadIdx.x & 31, ty = threadIdx.x >> 5;
#pragma unroll
    for (int t = 0; t < 4; t++)
        tile[ty + 8 * t][tx] = W[(size_t)(k0 + ty + 8 * t) * EE + n0 + tx];
    __syncthreads();
#pragma unroll
    for (int t = 0; t < 4; t++)
        Wt[(size_t)(n0 + ty + 8 * t) * EE + k0 + tx] = __float2half_rn(tile[tx][ty + 8 * t]);
}

// ---------------------------------------------------------------------------
// fp16 mma.sync GEMM (R14 verbatim): tile 128x128, k-tile 64, 2 CTAs/SM
// ---------------------------------------------------------------------------
#define GSMEM (3 * 32768 + 1024)

__device__ __forceinline__ void gemm_body(
    const __half* __restrict__ A, const __half* __restrict__ Bt,
    const float* __restrict__ bias, void* __restrict__ Cv,
    int mode, float scale, int L)
{
    extern __shared__ char dyn_sm[];
    char* sm = (char*)(((uintptr_t)dyn_sm + 1023) & ~(uintptr_t)1023);
    const uint32_t sb = smem_u32(sm);

    const int tid  = threadIdx.x;
    const int wid  = tid >> 5;
    const int lane = tid & 31;
    const int wm   = wid & 3;
    const int wn   = wid >> 2;
    const int m0 = blockIdx.y * 128;
    const int n0 = blockIdx.x * 128;

    const __half* Ap = A  + (size_t)m0 * 1024;
    const __half* Bp = Bt + (size_t)n0 * 1024;

    const int lrow16 = lane & 15;
    const int kh16   = lane >> 4;

    float acc[2][8][4];
#pragma unroll
    for (int mt = 0; mt < 2; mt++)
#pragma unroll
        for (int nt = 0; nt < 8; nt++)
#pragma unroll
            for (int c = 0; c < 4; c++) acc[mt][nt][c] = 0.f;

    auto prefetch = [&](int st, int kt) {
        const int k0 = kt * 64;
        const uint32_t ao = sb + st * 32768;
        const uint32_t bo = ao + 16384;
#pragma unroll
        for (int t = 0; t < 4; t++) {
            int idx = tid + t * 256;
            int r = idx >> 3, c = idx & 7;
            uint32_t sw = (uint32_t)(r * 128 + ((c ^ (r & 7)) << 4));
            cp16(ao + sw, Ap + (size_t)r * 1024 + k0 + c * 8);
            cp16(bo + sw, Bp + (size_t)r * 1024 + k0 + c * 8);
        }
    };

    prefetch(0, 0); CP_COMMIT();
    prefetch(1, 1); CP_COMMIT();

#pragma unroll 1
    for (int kt = 0; kt < 16; kt++) {
        CP_WAIT1();
        __syncthreads();
        if (kt + 2 < 16) prefetch((kt + 2) % 3, kt + 2);
        CP_COMMIT();

        const uint32_t ab = sb + (kt % 3) * 32768;
        const uint32_t bb = ab + 16384;
#pragma unroll
        for (int k16 = 0; k16 < 4; k16++) {
            const uint32_t kc = (uint32_t)(k16 * 2 + kh16);
            uint32_t af[2][4], bf[4][4];
#pragma unroll
            for (int mt = 0; mt < 2; mt++) {
                int r = wm * 32 + mt * 16 + lrow16;
                ldsm4(af[mt], ab + r * 128 + ((kc ^ (uint32_t)(r & 7)) << 4));
            }
#pragma unroll
            for (int g = 0; g < 4; g++) {
                int r = wn * 64 + g * 16 + lrow16;
                ldsm4(bf[g], bb + r * 128 + ((kc ^ (uint32_t)(r & 7)) << 4));
            }
#pragma unroll
            for (int mt = 0; mt < 2; mt++)
#pragma unroll
                for (int g = 0; g < 4; g++) {
                    mma_f16(acc[mt][2 * g],     af[mt], bf[g][0], bf[g][2]);
                    mma_f16(acc[mt][2 * g + 1], af[mt], bf[g][1], bf[g][3]);
                }
        }
    }

    const int rbase = lane >> 2;
    const int cbase = 2 * (lane & 3);
#pragma unroll
    for (int mt = 0; mt < 2; mt++) {
#pragma unroll
        for (int nt = 0; nt < 8; nt++) {
            int n = n0 + wn * 64 + nt * 8 + cbase;
#pragma unroll
            for (int half_ = 0; half_ < 2; half_++) {
                int m = m0 + wm * 32 + mt * 16 + rbase + half_ * 8;
                float vx = acc[mt][nt][half_ * 2 + 0];
                float vy = acc[mt][nt][half_ * 2 + 1];
                if (mode == 0) {
                    float2 v = {vx + bias[n], vy + bias[n + 1]};
                    *(float2*)&((float*)Cv)[(size_t)m * 1024 + n] = v;
                } else if (mode == 1) {
                    int b = m / L, l = m % L;
                    size_t o = (((size_t)(b * HH + (n >> 6)) * L + l) * DH) + (n & 63);
                    uint32_t h = pack_h2(vx * scale, vy * scale);
                    *(uint32_t*)&((__half*)Cv)[o] = h;
                } else {
                    int b = m / L, s = m % L;
                    size_t o = (((size_t)(b * HH + (n >> 6)) * DH) + (n & 63)) * (size_t)L + s;
                    ((__half*)Cv)[o]     = __float2half_rn(vx);
                    ((__half*)Cv)[o + L] = __float2half_rn(vy);
                }
            }
        }
    }
}

__global__ __launch_bounds__(256, 2)
void gemm_qkv_kernel(const __half* __restrict__ Atgt, const __half* __restrict__ Asrc,
                     const __half* __restrict__ Wt,
                     __half* __restrict__ Cq, __half* __restrict__ Ck, __half* __restrict__ Cvt)
{
    const int z = blockIdx.z;
    const __half* A = (z == 0) ? Atgt : Asrc;
    const __half* W = Wt + (size_t)z * EE * EE;
    __half* C = (z == 0) ? Cq : (z == 1) ? Ck : Cvt;
    gemm_body(A, W, nullptr, C, (z == 2) ? 2 : 1, (z == 0) ? 0.125f : 1.0f, (z == 0) ? TT : SS);
}

__global__ __launch_bounds__(256, 2)
void gemm_out_kernel(const __half* __restrict__ A, const __half* __restrict__ Wt,
                     const float* __restrict__ bias, float* __restrict__ C)
{
    gemm_body(A, Wt, bias, C, 0, 1.0f, TT);
}

// ---------------------------------------------------------------------------
// Fused flash-style attention, fp16 tensor path. NEW: amask tile staged into
// smem via cp.async (double-buffered, joint commit with KV) — replaces the
// 8-row-scattered fp32 LDGs with coalesced copies + cheap LDS.
// 256 threads, 2 CTAs/SM, 64 t-rows/block, 16 iters of 64-col tiles.
// ---------------------------------------------------------------------------
#define AT2 64
// byte offsets
#define B_Q    0                    // 64x64 fp16, 128B rows swizzled   8192
#define B_K    8192                 // 2 x 8192                        16384
#define B_V    24576                // 2 x 8192                        16384
#define B_SP   40960                // spad (fp32) 1024 floats          4096
#define B_PART 45056                // 128 floats                        512
#define B_SUM  45568                // 64 floats                         256
#define B_M    45824                // 2 x (64 x 68 fp32)              34816
#define ATTN_BYTES 80640
#define M_PITCH 68                  // floats per mask row (272B, 16B-aligned)
#define RED_PITCH 72                // k-split O reduce (floats), reuses K/V region

__global__ __launch_bounds__(256, 2)
void attn_kernel(const __half* __restrict__ Q, const __half* __restrict__ K,
                 const __half* __restrict__ Vt,
                 const float* __restrict__ tpad, const float* __restrict__ spad,
                 const float* __restrict__ amask, const int* __restrict__ causal_p,
                 float* __restrict__ attn_out, __half* __restrict__ P)
{
    extern __shared__ float smf[];
    const uint32_t base = smem_u32(smf);
    const uint32_t q_b  = base + B_Q;
    const uint32_t k_b  = base + B_K;
    const uint32_t v_b  = base + B_V;
    const uint32_t sp_b = base + B_SP;
    const uint32_t m_b  = base + B_M;
    float* s_sp   = smf + B_SP / 4;
    float* s_part = smf + B_PART / 4;
    float* s_sum  = smf + B_SUM / 4;
    float* s_red  = smf + B_K / 4;   // reused after main loop (barrier-guarded)

    const int tid = threadIdx.x;
    const int bh  = blockIdx.y;
    const int b   = bh >> 4;
    const int h   = bh & 15;
    const int t0  = blockIdx.x * AT2;
    const bool causal = (causal_p[0] != 0);

    const size_t qbase  = ((size_t)bh * TT + t0) * DH;
    const size_t kbase  = (size_t)bh * SS * DH;
    const size_t vtbase = (size_t)bh * DH * SS;

    const int lane  = tid & 31;
    const int wid   = tid >> 5;
    const int wm    = wid & 3;    // m16 group
    const int wn    = wid >> 2;   // n32 group (0/1); also PV k-split id
    const int lrow16 = lane & 15;
    const int kh16   = lane >> 4;
    const int rbase = lane >> 2;
    const int cbase = 2 * (lane & 3);

    const int r0 = wm * 16 + rbase;
    const int r1 = r0 + 8;
    const float tm0 = tpad[b * TT + t0 + r0];
    const float tm1 = tpad[b * TT + t0 + r1];

    auto prefetch_kv = [&](int it) {
        const uint32_t kb = k_b + (uint32_t)(it & 1) * 8192;
        const uint32_t vb = v_b + (uint32_t)(it & 1) * 8192;
        const int c0 = it * 64;
#pragma unroll
        for (int t = 0; t < 2; t++) {
            int idx = tid + t * 256;
            int r = idx >> 3, c = idx & 7;
            uint32_t sw = (uint32_t)(r * 128 + ((c ^ (r & 7)) << 4));
            cp16(kb + sw, K + kbase + (size_t)(c0 + r) * DH + c * 8);
            cp16(vb + sw, Vt + vtbase + (size_t)r * SS + c0 + c * 8);
        }
    };
    auto prefetch_mask = [&](int it) {
        const uint32_t mb = m_b + (uint32_t)(it & 1) * (64 * M_PITCH * 4);
        const int c0 = it * 64;
#pragma unroll
        for (int t = 0; t < 4; t++) {
            int idx = tid + t * 256;
            int r = idx >> 4, c = idx & 15;
            cp16(mb + r * (M_PITCH * 4) + c * 16,
                 amask + ((size_t)b * TT + t0 + r) * SS + c0 + c * 4);
        }
    };

    // prologue: [Q + spad + KV0 + M0] , [KV1 + M1]
    {
#pragma unroll
        for (int t = 0; t < 2; t++) {
            int idx = tid + t * 256;
            int r = idx >> 3, c = idx & 7;
            cp16(q_b + r * 128 + ((c ^ (r & 7)) << 4), Q + qbase + (size_t)r * DH + c * 8);
        }
        cp16(sp_b + tid * 16, spad + b * SS + tid * 4);
    }
    prefetch_kv(0);
    prefetch_mask(0);
    CP_COMMIT();
    prefetch_kv(1);
    prefetch_mask(1);
    CP_COMMIT();

    CP_WAIT1();
    __syncthreads();

    // preload Q fragments: m16 x k64 = 4 ldsm.x4
    uint32_t qf[4][4];
#pragma unroll
    for (int k16 = 0; k16 < 4; k16++) {
        int r = wm * 16 + lrow16;
        uint32_t kc = (uint32_t)(k16 * 2 + kh16);
        ldsm4(qf[k16], q_b + r * 128 + ((kc ^ (uint32_t)(r & 7)) << 4));
    }

    float rs0 = 0.f, rs1 = 0.f;
    float oacc[8][4];                        // m16 x n64 partial (own k slice)
#pragma unroll
    for (int n8 = 0; n8 < 8; n8++)
#pragma unroll
        for (int c = 0; c < 4; c++) oacc[n8][c] = 0.f;

#pragma unroll 1
    for (int it = 0; it < 16; it++) {
        if (it > 0) {
            CP_WAIT1();
            __syncthreads();
        }
        const int c0 = it * 64;
        const uint32_t kb = k_b + (uint32_t)(it & 1) * 8192;
        const uint32_t vb = v_b + (uint32_t)(it & 1) * 8192;
        const float* s_m = smf + B_M / 4 + (it & 1) * (64 * M_PITCH);

        // S = Q @ K^T  (warp m16 x n32, k = 64 via 4 k16 steps)
        float acc[4][4];
#pragma unroll
        for (int n8 = 0; n8 < 4; n8++)
#pragma unroll
            for (int c = 0; c < 4; c++) acc[n8][c] = 0.f;

#pragma unroll
        for (int k16 = 0; k16 < 4; k16++) {
            uint32_t kc = (uint32_t)(k16 * 2 + kh16);
#pragma unroll
            for (int ng = 0; ng < 2; ng++) {
                int r = wn * 32 + ng * 16 + lrow16;
                uint32_t bf[4];
                ldsm4(bf, kb + r * 128 + ((kc ^ (uint32_t)(r & 7)) << 4));
                mma_f16(acc[2 * ng],     qf[k16], bf[0], bf[2]);
                mma_f16(acc[2 * ng + 1], qf[k16], bf[1], bf[3]);
            }
        }

        // exp (no max shift), attn write (unnormalized fp32), row sums
        const int tg0 = t0 + r0, tg1 = t0 + r1;
#pragma unroll
        for (int n8 = 0; n8 < 4; n8++) {
            int scl = wn * 32 + n8 * 8 + cbase;
            int sc  = c0 + scl;
            float2 sp = *(const float2*)&s_sp[sc];
            float2 am0 = *(const float2*)&s_m[r0 * M_PITCH + scl];
            float2 am1 = *(const float2*)&s_m[r1 * M_PITCH + scl];

            float m00 = tm0 * sp.x * am0.x;
            float m01 = tm0 * sp.y * am0.y;
            float m10 = tm1 * sp.x * am1.x;
            float m11 = tm1 * sp.y * am1.y;
            if (causal) {
                if (sc > tg0)     m00 = 0.f;
                if (sc + 1 > tg0) m01 = 0.f;
                if (sc > tg1)     m10 = 0.f;
                if (sc + 1 > tg1) m11 = 0.f;
            }
            float e00 = __expf(acc[n8][0] + m00);
            float e01 = __expf(acc[n8][1] + m01);
            float e10 = __expf(acc[n8][2] + m10);
            float e11 = __expf(acc[n8][3] + m11);
            rs0 += e00 + e01;
            rs1 += e10 + e11;

            if (attn_out) {
                float2 w0 = {e00, e01}, w1 = {e10, e11};
                *(float2*)&attn_out[((size_t)bh * TT + tg0) * SS + sc] = w0;
                *(float2*)&attn_out[((size_t)bh * TT + tg1) * SS + sc] = w1;
            }
            acc[n8][0] = e00; acc[n8][1] = e01;
            acc[n8][2] = e10; acc[n8][3] = e11;
        }

        // O += P @ V over this warp's own 32 k-cols (2 k16 chunks).
#pragma unroll
        for (int kp = 0; kp < 2; kp++) {
            int j0 = 2 * kp, j1 = 2 * kp + 1;
            uint32_t af[4];
            af[0] = pack_h2(acc[j0][0], acc[j0][1]);
            af[1] = pack_h2(acc[j0][2], acc[j0][3]);
            af[2] = pack_h2(acc[j1][0], acc[j1][1]);
            af[3] = pack_h2(acc[j1][2], acc[j1][3]);

            uint32_t kc = (uint32_t)((wn * 2 + kp) * 2 + kh16);
#pragma unroll
            for (int nt = 0; nt < 4; nt++) {
                int r = nt * 16 + lrow16;
                uint32_t bf[4];
                ldsm4(bf, vb + r * 128 + ((kc ^ (uint32_t)(r & 7)) << 4));
                mma_f16(oacc[2 * nt],     af, bf[0], bf[2]);
                mma_f16(oacc[2 * nt + 1], af, bf[1], bf[3]);
            }
        }
        __syncthreads();   // K/V/mask reads done before buffers refilled

        if (it + 2 < 16) {
            prefetch_kv(it + 2);
            prefetch_mask(it + 2);
            CP_COMMIT();
        }
    }

    // row-sum reduction: quad shuffle, then 2-way cross-warp via smem
    rs0 += __shfl_xor_sync(0xffffffffu, rs0, 1);
    rs0 += __shfl_xor_sync(0xffffffffu, rs0, 2);
    rs1 += __shfl_xor_sync(0xffffffffu, rs1, 1);
    rs1 += __shfl_xor_sync(0xffffffffu, rs1, 2);
    if ((lane & 3) == 0) {
        s_part[wn * 64 + r0] = rs0;
        s_part[wn * 64 + r1] = rs1;
    }
    // k-split partials: wn==1 stores O partial to s_red (reuses K/V region)
    if (wn == 1) {
#pragma unroll
        for (int n8 = 0; n8 < 8; n8++) {
            int cc = n8 * 8 + cbase;
            *(float2*)&s_red[r0 * RED_PITCH + cc] = *(float2*)&oacc[n8][0];
            *(float2*)&s_red[r1 * RED_PITCH + cc] = *(float2*)&oacc[n8][2];
        }
    }
    if (attn_out) asm volatile("membar.cta;" ::: "memory");
    __syncthreads();
    if (tid < 64) {
        s_sum[tid] = 1.f / (s_part[tid] + s_part[64 + tid]);
    }
    __syncthreads();

    // wn==0 warps: combine k-split partials, scale, write P gmem (fp16)
    if (wn == 0) {
        float inv0 = s_sum[r0], inv1 = s_sum[r1];
#pragma unroll
        for (int n8 = 0; n8 < 8; n8++) {
            int cc = n8 * 8 + cbase;
            float2 q0 = *(float2*)&s_red[r0 * RED_PITCH + cc];
            float2 q1 = *(float2*)&s_red[r1 * RED_PITCH + cc];
            uint32_t h0 = pack_h2((oacc[n8][0] + q0.x) * inv0, (oacc[n8][1] + q0.y) * inv0);
            uint32_t h1 = pack_h2((oacc[n8][2] + q1.x) * inv1, (oacc[n8][3] + q1.y) * inv1);
            *(uint32_t*)&P[((size_t)(t0 + r0) * BX + b) * EE + h * DH + cc] = h0;
            *(uint32_t*)&P[((size_t)(t0 + r1) * BX + b) * EE + h * DH + cc] = h1;
        }
    }

    // rescale this block's attn rows (unnormalized -> probabilities)
    if (attn_out) {
        const int r = tid >> 2;
        const int l4 = tid & 3;
        const float inv = s_sum[r];
        float* row = attn_out + ((size_t)bh * TT + t0 + r) * SS;
#pragma unroll 8
        for (int i = 0; i < 64; i++) {
            float4 v = *(float4*)&row[l4 * 4 + i * 16];
            v.x *= inv; v.y *= inv; v.z *= inv; v.w *= inv;
            *(float4*)&row[l4 * 4 + i * 16] = v;
        }
    }
}

// ---------------------------------------------------------------------------
// Launch
// ---------------------------------------------------------------------------
extern "C" void kernel_launch(void* const* d_in, const int* in_sizes, int n_in,
                              void* d_out, int out_size)
{
    const float* src   = (const float*)d_in[0];
    const float* tgt   = (const float*)d_in[1];
    const float* spad  = (const float*)d_in[2];
    const float* tpad  = (const float*)d_in[3];
    const float* amask = (const float*)d_in[4];
    const int*   caus  = (const int*)  d_in[5];
    const float* Wq    = (const float*)d_in[6];
    const float* Wk    = (const float*)d_in[7];
    const float* Wv    = (const float*)d_in[8];
    const float* Wo    = (const float*)d_in[9];
    const float* bo    = (const float*)d_in[10];

    const size_t OUT_N  = (size_t)TT * BX * EE;
    const size_t ATTN_N = (size_t)BX * HH * TT * SS;

    float* out_p  = nullptr;
    float* attn_p = nullptr;
    if ((size_t)out_size == OUT_N + ATTN_N) {
        out_p  = (float*)d_out;
        attn_p = (float*)d_out + OUT_N;
    } else if ((size_t)out_size == ATTN_N) {
        attn_p = (float*)d_out;
    } else {
        out_p  = (float*)d_out;
    }

    __half *Qp, *Kp, *Vtp, *Pp, *Wtp, *Arp, *Brp;
    cudaGetSymbolAddress((void**)&Qp, g_Q);
    cudaGetSymbolAddress((void**)&Kp, g_K);
    cudaGetSymbolAddress((void**)&Vtp, g_Vt);
    cudaGetSymbolAddress((void**)&Pp, g_P);
    cudaGetSymbolAddress((void**)&Wtp, g_Wt);
    cudaGetSymbolAddress((void**)&Arp, g_Ar);
    cudaGetSymbolAddress((void**)&Brp, g_Br);

    cudaFuncSetAttribute(attn_kernel, cudaFuncAttributeMaxDynamicSharedMemorySize, ATTN_BYTES);
    cudaFuncSetAttribute(gemm_qkv_kernel, cudaFuncAttributeMaxDynamicSharedMemorySize, GSMEM);
    cudaFuncSetAttribute(gemm_out_kernel, cudaFuncAttributeMaxDynamicSharedMemorySize, GSMEM);

    // pre-round inputs + transpose weights (fp16)
    round_f16_kernel<<<dim3(512, 1, 2), 256>>>(tgt, src, Arp, Brp);
    transpose_f16_kernel<<<dim3(32, 32, 4), 256>>>(Wq, Wk, Wv, Wo, Wtp);

    // merged QKV projections (2 CTAs/SM)
    gemm_qkv_kernel<<<dim3(8, 32, 3), 256, GSMEM>>>(Arp, Brp, Wtp, Qp, Kp, Vtp);

    // fused attention (2 CTAs/SM)
    dim3 agrid(TT / AT2, BX * HH);   // (16, 64)
    attn_kernel<<<agrid, dim3(256), ATTN_BYTES>>>(Qp, Kp, Vtp, tpad, spad, amask,
                                                  caus, attn_p, Pp);

    // output projection (2 CTAs/SM)
    if (out_p) {
        gemm_out_kernel<<<dim3(8, 32), 256, GSMEM>>>(Pp, Wtp + 3 * (size_t)EE * EE, bo, out_p);
    }
}